// round 2
// baseline (speedup 1.0000x reference)
#include <cuda_runtime.h>
#include <math.h>

#define B_TOT 3072
#define NTOK  64
#define DIM   128
#define NH    4
#define HD    32
#define NWIN  192
#define STR   132              // padded row stride (floats): 132 % 32 == 4 -> conflict-free f4 lanes
#define QSCALE 0.1767766952966369f   // 32^-0.5
#define OUTS   0.8f                  // 1 - lambda_init

__device__ float g_pb[NH * NTOK * NTOK];
__device__ float g_lam;

// ---------------------------------------------------------------------------
// Prep: polar-MLP relative-position bias table (window-invariant) + lambda
// ---------------------------------------------------------------------------
__global__ void prep_kernel(const float* __restrict__ Wp1, const float* __restrict__ bp1,
                            const float* __restrict__ Wp2, const float* __restrict__ bp2,
                            const float* __restrict__ lq1, const float* __restrict__ lk1,
                            const float* __restrict__ lq2, const float* __restrict__ lk2)
{
    int idx = blockIdx.x * blockDim.x + threadIdx.x;   // 0..4095 (n*64+m)
    if (idx < NTOK * NTOK) {
        int i = idx >> 6, j = idx & 63;
        float dx = (float)(i & 7) - (float)(j & 7);
        float dy = -((float)(i >> 3) - (float)(j >> 3));
        float r  = sqrtf(dx * dx + dy * dy + 1e-9f);
        float th = atan2f(dx, dy);
        float p0 = r * 0.10101525445522107f;                         // / sqrt(98)
        float p1 = (th + 3.14159265358979323846f) * 0.15915494309189535f; // /(2pi)
        float o0 = __ldg(bp2 + 0), o1 = __ldg(bp2 + 1), o2 = __ldg(bp2 + 2), o3 = __ldg(bp2 + 3);
        for (int jj = 0; jj < 64; jj++) {
            float hv = fmaf(p0, __ldg(Wp1 + jj * 2), fmaf(p1, __ldg(Wp1 + jj * 2 + 1), __ldg(bp1 + jj)));
            float g  = 0.5f * hv * (1.0f + erff(hv * 0.7071067811865476f));  // exact GELU
            o0 = fmaf(g, __ldg(Wp2 +       jj), o0);
            o1 = fmaf(g, __ldg(Wp2 +  64 + jj), o1);
            o2 = fmaf(g, __ldg(Wp2 + 128 + jj), o2);
            o3 = fmaf(g, __ldg(Wp2 + 192 + jj), o3);
        }
        g_pb[          idx] = o0;
        g_pb[ 4096 +   idx] = o1;
        g_pb[ 8192 +   idx] = o2;
        g_pb[12288 +   idx] = o3;
    }
    if (idx == 0) {
        float s1 = 0.f, s2 = 0.f;
        for (int k = 0; k < 16; k++) {
            s1 = fmaf(__ldg(lq1 + k), __ldg(lk1 + k), s1);
            s2 = fmaf(__ldg(lq2 + k), __ldg(lk2 + k), s2);
        }
        g_lam = expf(s1) - expf(s2) + 0.2f;   // lambda_init = 0.2 (layer 0)
    }
}

// ---------------------------------------------------------------------------
// Main fused kernel: one CTA per window, 256 threads
// smem (floats):
//   xs  [64][132]  @ 0       (reused as os after GEMMs)
//   qs  [64][132]  @ 8448    (reused as out staging after attention)
//   ks  [64][132]  @ 16896
//   vs  [64][132]  @ 25344
//   q2s [64][132]  @ 33792
//   k2s [64][132]  @ 42240
//   wb  [32][132]  @ 50688   (weight staging; also att[64][65] scratch)
// total 54912 floats = 219648 B
// ---------------------------------------------------------------------------
__global__ __launch_bounds__(256) void wattn_kernel(
    const float* __restrict__ x,     const float* __restrict__ mask,
    const float* __restrict__ Wqkv,  const float* __restrict__ bqkv,
    const float* __restrict__ Wqkv2, const float* __restrict__ bqkv2,
    const float* __restrict__ subln_w,
    const float* __restrict__ Wproj, const float* __restrict__ bproj,
    float* __restrict__ out)
{
    extern __shared__ float sm[];
    float* xs   = sm;
    float* qs   = sm + 8448;
    float* ks   = sm + 16896;
    float* vs   = sm + 25344;
    float* q2s  = sm + 33792;
    float* k2s  = sm + 42240;
    float* wb   = sm + 50688;
    float* att  = wb;
    float* os   = xs;
    float* outb = qs;

    const int b = blockIdx.x;
    const int t = threadIdx.x;

    // ---- load x tile (coalesced f4) ----
    const float4* xg = (const float4*)(x + (size_t)b * (NTOK * DIM));
    #pragma unroll
    for (int i = 0; i < 8; i++) {
        int idx = t + i * 256;
        int n = idx >> 5, kk = idx & 31;
        float4 v = __ldg(xg + idx);
        *(float4*)(xs + n * STR + kk * 4) = v;
    }
    __syncthreads();

    // ---- fused q/k/v/q2/k2 GEMM: 640 output cols in 20 chunks of 32 ----
    const int tx = t & 15, ty = t >> 4;
    #pragma unroll 1
    for (int ch = 0; ch < 20; ch++) {
        const int c0 = ch * 32;
        #pragma unroll
        for (int i = 0; i < 4; i++) {                    // stage 32x128 weight tile
            int idx = t + i * 256;
            int r = idx >> 5, kk = idx & 31;
            int cg = c0 + r;
            const float4* src = (cg < 384) ? ((const float4*)(Wqkv  + cg * DIM)        + kk)
                                           : ((const float4*)(Wqkv2 + (cg - 384) * DIM) + kk);
            *(float4*)(wb + r * STR + kk * 4) = __ldg(src);
        }
        __syncthreads();

        float acc[2][4];
        #pragma unroll
        for (int j = 0; j < 2; j++)
            #pragma unroll
            for (int i = 0; i < 4; i++) acc[j][i] = 0.f;

        #pragma unroll 8
        for (int kk = 0; kk < 32; kk++) {
            float4 w0 = *(const float4*)(wb + ty        * STR + kk * 4);
            float4 w1 = *(const float4*)(wb + (ty + 16) * STR + kk * 4);
            #pragma unroll
            for (int i = 0; i < 4; i++) {
                float4 xv = *(const float4*)(xs + (tx + 16 * i) * STR + kk * 4);
                acc[0][i] = fmaf(xv.x, w0.x, fmaf(xv.y, w0.y, fmaf(xv.z, w0.z, fmaf(xv.w, w0.w, acc[0][i]))));
                acc[1][i] = fmaf(xv.x, w1.x, fmaf(xv.y, w1.y, fmaf(xv.z, w1.z, fmaf(xv.w, w1.w, acc[1][i]))));
            }
        }

        #pragma unroll
        for (int j = 0; j < 2; j++) {
            int cg = c0 + ty + 16 * j;
            float bias, mult = 1.0f; float* dst; int col;
            if      (cg < 128) { bias = __ldg(bqkv + cg);        dst = qs;  col = cg;       mult = QSCALE; }
            else if (cg < 256) { bias = __ldg(bqkv + cg);        dst = ks;  col = cg - 128; }
            else if (cg < 384) { bias = __ldg(bqkv + cg);        dst = vs;  col = cg - 256; }
            else if (cg < 512) { bias = __ldg(bqkv2 + cg - 384); dst = q2s; col = cg - 384; mult = QSCALE; }
            else               { bias = __ldg(bqkv2 + cg - 384); dst = k2s; col = cg - 512; }
            #pragma unroll
            for (int i = 0; i < 4; i++)
                dst[(tx + 16 * i) * STR + col] = (acc[j][i] + bias) * mult;
        }
        __syncthreads();
    }

    // ---- differential attention, per head ----
    const float lam = g_lam;
    const float* mk = mask + (size_t)(b % NWIN) * (NTOK * NTOK);
    const int n = t >> 2, qd = t & 3;     // 4 threads per token row

    #pragma unroll 1
    for (int h = 0; h < NH; h++) {
        const int ho = h * HD;
        float4 qv[8], q2v[8];
        #pragma unroll
        for (int i = 0; i < 8; i++) {
            qv[i]  = *(const float4*)(qs  + n * STR + ho + i * 4);
            q2v[i] = *(const float4*)(q2s + n * STR + ho + i * 4);
        }

        float lg[16];
        #pragma unroll 4
        for (int j = 0; j < 16; j++) {
            int m = qd + 4 * j;
            float a = 0.f, a2 = 0.f;
            #pragma unroll
            for (int i = 0; i < 8; i++) {
                float4 kv  = *(const float4*)(ks  + m * STR + ho + i * 4);
                float4 kv2 = *(const float4*)(k2s + m * STR + ho + i * 4);
                a  = fmaf(qv[i].x,  kv.x,  fmaf(qv[i].y,  kv.y,  fmaf(qv[i].z,  kv.z,  fmaf(qv[i].w,  kv.w,  a))));
                a2 = fmaf(q2v[i].x, kv2.x, fmaf(q2v[i].y, kv2.y, fmaf(q2v[i].z, kv2.z, fmaf(q2v[i].w, kv2.w, a2))));
            }
            lg[j] = a - lam * a2 + __ldg(g_pb + h * 4096 + n * 64 + m) + __ldg(mk + n * 64 + m);
        }

        // softmax across the row (4-lane cooperative)
        float M = lg[0];
        #pragma unroll
        for (int j = 1; j < 16; j++) M = fmaxf(M, lg[j]);
        M = fmaxf(M, __shfl_xor_sync(0xffffffffu, M, 1));
        M = fmaxf(M, __shfl_xor_sync(0xffffffffu, M, 2));
        float S = 0.f;
        #pragma unroll
        for (int j = 0; j < 16; j++) { lg[j] = __expf(lg[j] - M); S += lg[j]; }
        S += __shfl_xor_sync(0xffffffffu, S, 1);
        S += __shfl_xor_sync(0xffffffffu, S, 2);
        float inv = 1.0f / S;
        #pragma unroll
        for (int j = 0; j < 16; j++) att[n * 65 + qd + 4 * j] = lg[j] * inv;
        __syncthreads();

        // o = P @ V  (each thread: 8 head-dims of its row)
        float o[8] = {0.f, 0.f, 0.f, 0.f, 0.f, 0.f, 0.f, 0.f};
        #pragma unroll 8
        for (int m = 0; m < 64; m++) {
            float p = att[n * 65 + m];
            float4 v0 = *(const float4*)(vs + m * STR + ho + qd * 8);
            float4 v1 = *(const float4*)(vs + m * STR + ho + qd * 8 + 4);
            o[0] = fmaf(p, v0.x, o[0]); o[1] = fmaf(p, v0.y, o[1]);
            o[2] = fmaf(p, v0.z, o[2]); o[3] = fmaf(p, v0.w, o[3]);
            o[4] = fmaf(p, v1.x, o[4]); o[5] = fmaf(p, v1.y, o[5]);
            o[6] = fmaf(p, v1.z, o[6]); o[7] = fmaf(p, v1.w, o[7]);
        }

        // RMSNorm over head_dim + subln weight + (1 - lambda_init)
        float ss = 0.f;
        #pragma unroll
        for (int k = 0; k < 8; k++) ss = fmaf(o[k], o[k], ss);
        ss += __shfl_xor_sync(0xffffffffu, ss, 1);
        ss += __shfl_xor_sync(0xffffffffu, ss, 2);
        float rs = rsqrtf(ss * (1.0f / 32.0f) + 1e-9f);
        #pragma unroll
        for (int k = 0; k < 8; k++) {
            int hd = qd * 8 + k;
            os[n * STR + ho + hd] = o[k] * rs * __ldg(subln_w + hd) * OUTS;
        }
        __syncthreads();   // protects att (next head) and os (proj)
    }

    // ---- output projection: 128 cols in 4 chunks of 32 ----
    #pragma unroll 1
    for (int ch = 0; ch < 4; ch++) {
        const int c0 = ch * 32;
        #pragma unroll
        for (int i = 0; i < 4; i++) {
            int idx = t + i * 256;
            int r = idx >> 5, kk = idx & 31;
            *(float4*)(wb + r * STR + kk * 4) = __ldg((const float4*)(Wproj + (c0 + r) * DIM) + kk);
        }
        __syncthreads();

        float acc[2][4];
        #pragma unroll
        for (int j = 0; j < 2; j++)
            #pragma unroll
            for (int i = 0; i < 4; i++) acc[j][i] = 0.f;

        #pragma unroll 8
        for (int kk = 0; kk < 32; kk++) {
            float4 w0 = *(const float4*)(wb + ty        * STR + kk * 4);
            float4 w1 = *(const float4*)(wb + (ty + 16) * STR + kk * 4);
            #pragma unroll
            for (int i = 0; i < 4; i++) {
                float4 ov = *(const float4*)(os + (tx + 16 * i) * STR + kk * 4);
                acc[0][i] = fmaf(ov.x, w0.x, fmaf(ov.y, w0.y, fmaf(ov.z, w0.z, fmaf(ov.w, w0.w, acc[0][i]))));
                acc[1][i] = fmaf(ov.x, w1.x, fmaf(ov.y, w1.y, fmaf(ov.z, w1.z, fmaf(ov.w, w1.w, acc[1][i]))));
            }
        }
        #pragma unroll
        for (int j = 0; j < 2; j++)
            #pragma unroll
            for (int i = 0; i < 4; i++)
                outb[(tx + 16 * i) * STR + c0 + ty + 16 * j] = acc[j][i];
        __syncthreads();
    }

    // ---- coalesced write-out with bias ----
    float* og = out + (size_t)b * (NTOK * DIM);
    #pragma unroll
    for (int i = 0; i < 32; i++) {
        int idx = t + i * 256;
        int nn = idx >> 7, c = idx & 127;
        og[idx] = outb[nn * STR + c] + __ldg(bproj + c);
    }
}

// ---------------------------------------------------------------------------
extern "C" void kernel_launch(void* const* d_in, const int* in_sizes, int n_in,
                              void* d_out, int out_size)
{
    const float* x      = (const float*)d_in[0];
    const float* mask   = (const float*)d_in[1];
    const float* Wqkv   = (const float*)d_in[2];
    const float* bqkv   = (const float*)d_in[3];
    const float* Wqkv2  = (const float*)d_in[4];
    const float* bqkv2  = (const float*)d_in[5];
    const float* Wp1    = (const float*)d_in[6];
    const float* bp1    = (const float*)d_in[7];
    const float* Wp2    = (const float*)d_in[8];
    const float* bp2    = (const float*)d_in[9];
    const float* lq1    = (const float*)d_in[10];
    const float* lk1    = (const float*)d_in[11];
    const float* lq2    = (const float*)d_in[12];
    const float* lk2    = (const float*)d_in[13];
    const float* subln  = (const float*)d_in[14];
    const float* Wproj  = (const float*)d_in[15];
    const float* bproj  = (const float*)d_in[16];
    float* out = (float*)d_out;

    const int SMEM = 54912 * (int)sizeof(float);   // 219648 B
    cudaFuncSetAttribute(wattn_kernel, cudaFuncAttributeMaxDynamicSharedMemorySize, SMEM);

    prep_kernel<<<16, 256>>>(Wp1, bp1, Wp2, bp2, lq1, lk1, lq2, lk2);
    wattn_kernel<<<B_TOT, 256, SMEM>>>(x, mask, Wqkv, bqkv, Wqkv2, bqkv2,
                                       subln, Wproj, bproj, out);
}

// round 4
// speedup vs baseline: 1.1085x; 1.1085x over previous
#include <cuda_runtime.h>
#include <math.h>

typedef unsigned long long u64;

#define B_TOT 3072
#define NTOK  64
#define DIM   128
#define NH    4
#define HD    32
#define NWIN  192
#define QSCALE 0.1767766952966369f   // 32^-0.5
#define OUTS   0.8f                  // 1 - lambda_init

// ---------------- packed f32x2 helpers ----------------
__device__ __forceinline__ void ffma2(u64& d, u64 a, u64 b) {
    asm("fma.rn.f32x2 %0, %1, %2, %0;" : "+l"(d) : "l"(a), "l"(b));
}
__device__ __forceinline__ u64 pack2(float x, float y) {
    u64 r; asm("mov.b64 %0, {%1, %2};" : "=l"(r) : "f"(x), "f"(y)); return r;
}
__device__ __forceinline__ float lo2(u64 u) { return __uint_as_float((unsigned)u); }
__device__ __forceinline__ float hi2(u64 u) { return __uint_as_float((unsigned)(u >> 32)); }
__device__ __forceinline__ float sum2(u64 u) { return lo2(u) + hi2(u); }

// swizzled f4-unit index inside a [64 rows][32 f4] tile (conflict-free for all
// access patterns used below; stride 128 floats, zero padding)
__device__ __forceinline__ int SWZ(int row, int g) { return row * 32 + (g ^ (row & 31)); }

__device__ float g_pb[NH * NTOK * NTOK];
__device__ float g_pbm[NWIN * NH * NTOK * NTOK];   // mask + pos-bias, folded
__device__ float g_lam;

// ---------------------------------------------------------------------------
// Prep 1: polar-MLP relative-position bias table + lambda
// ---------------------------------------------------------------------------
__global__ void prep1_kernel(const float* __restrict__ Wp1, const float* __restrict__ bp1,
                             const float* __restrict__ Wp2, const float* __restrict__ bp2,
                             const float* __restrict__ lq1, const float* __restrict__ lk1,
                             const float* __restrict__ lq2, const float* __restrict__ lk2)
{
    int idx = blockIdx.x * blockDim.x + threadIdx.x;   // 0..4095 (n*64+m)
    if (idx < NTOK * NTOK) {
        int i = idx >> 6, j = idx & 63;
        float dx = (float)(i & 7) - (float)(j & 7);
        float dy = -((float)(i >> 3) - (float)(j >> 3));
        float r  = sqrtf(dx * dx + dy * dy + 1e-9f);
        float th = atan2f(dx, dy);
        float p0 = r * 0.10101525445522107f;                               // / sqrt(98)
        float p1 = (th + 3.14159265358979323846f) * 0.15915494309189535f;  // /(2pi)
        float o0 = __ldg(bp2 + 0), o1 = __ldg(bp2 + 1), o2 = __ldg(bp2 + 2), o3 = __ldg(bp2 + 3);
        for (int jj = 0; jj < 64; jj++) {
            float hv = fmaf(p0, __ldg(Wp1 + jj * 2), fmaf(p1, __ldg(Wp1 + jj * 2 + 1), __ldg(bp1 + jj)));
            float g  = 0.5f * hv * (1.0f + erff(hv * 0.7071067811865476f));   // exact GELU
            o0 = fmaf(g, __ldg(Wp2 +       jj), o0);
            o1 = fmaf(g, __ldg(Wp2 +  64 + jj), o1);
            o2 = fmaf(g, __ldg(Wp2 + 128 + jj), o2);
            o3 = fmaf(g, __ldg(Wp2 + 192 + jj), o3);
        }
        g_pb[          idx] = o0;
        g_pb[ 4096 +   idx] = o1;
        g_pb[ 8192 +   idx] = o2;
        g_pb[12288 +   idx] = o3;
    }
    if (idx == 0) {
        float s1 = 0.f, s2 = 0.f;
        for (int k = 0; k < 16; k++) {
            s1 = fmaf(__ldg(lq1 + k), __ldg(lk1 + k), s1);
            s2 = fmaf(__ldg(lq2 + k), __ldg(lk2 + k), s2);
        }
        g_lam = expf(s1) - expf(s2) + 0.2f;   // lambda_init = 0.2 (layer 0)
    }
}

// Prep 2: fold window mask into the bias table: pbm[w][h][n*64+m]
__global__ void prep2_kernel(const float* __restrict__ mask)
{
    int idx = blockIdx.x * 256 + threadIdx.x;          // 0 .. 3145727
    int w    = idx >> 14;                              // / (4*4096)
    int rest = idx & 16383;                            // h*4096 + nm
    int nm   = idx & 4095;
    g_pbm[idx] = g_pb[rest] + __ldg(mask + w * 4096 + nm);
}

// ---------------------------------------------------------------------------
// 64x64x128 register-blocked GEMM piece: src[64][128] @ w[64 cols][128]
// thread (tx,ty): rows ty*8..ty*8+7, cols {tx, tx+32}; acc pairs over k
// ---------------------------------------------------------------------------
__device__ __forceinline__ void gemm64(const float* __restrict__ src,
                                       const float* __restrict__ wsm,
                                       int tx, int ty, u64 acc[8][2])
{
    const ulonglong2* s = (const ulonglong2*)src;
    const ulonglong2* w = (const ulonglong2*)wsm;
    #pragma unroll
    for (int i = 0; i < 8; i++) { acc[i][0] = 0ull; acc[i][1] = 0ull; }
    #pragma unroll 2
    for (int kk = 0; kk < 32; kk++) {
        ulonglong2 w0 = w[tx * 32 + (kk ^ tx)];            // col tx
        ulonglong2 w1 = w[(tx + 32) * 32 + (kk ^ tx)];     // col tx+32 (same xor: (tx+32)&31==tx)
        #pragma unroll
        for (int i = 0; i < 8; i++) {
            int r = ty * 8 + i;
            ulonglong2 xv = s[r * 32 + (kk ^ (r & 31))];   // broadcast across warp
            ffma2(acc[i][0], xv.x, w0.x);
            ffma2(acc[i][0], xv.y, w0.y);
            ffma2(acc[i][1], xv.x, w1.x);
            ffma2(acc[i][1], xv.y, w1.y);
        }
    }
}

// ---------------------------------------------------------------------------
// Main fused kernel: one CTA per window, 256 threads.
// smem (floats, all [64][128] XOR-swizzled, no padding):
//   xs  @ 0      (reused as os)
//   qs  @ 8192   (reused as proj output staging)
//   ks  @ 16384
//   vs  @ 24576
//   q2s @ 32768
//   k2s @ 40960
//   wb  @ 49152  (weight staging; reused as att[64][68])
// total 57344 floats = 229376 B
// ---------------------------------------------------------------------------
__global__ __launch_bounds__(256) void wattn_kernel(
    const float* __restrict__ x,
    const float* __restrict__ Wqkv,  const float* __restrict__ bqkv,
    const float* __restrict__ Wqkv2, const float* __restrict__ bqkv2,
    const float* __restrict__ subln_w,
    const float* __restrict__ Wproj, const float* __restrict__ bproj,
    float* __restrict__ out)
{
    extern __shared__ float sm[];
    float* xs  = sm;
    float* qs  = sm + 8192;
    float* ks  = sm + 16384;
    float* vs  = sm + 24576;
    float* q2s = sm + 32768;
    float* k2s = sm + 40960;
    float* wb  = sm + 49152;
    float* att = wb;
    float* os  = xs;

    const int b = blockIdx.x;
    const int t = threadIdx.x;
    const int tx = t & 31, ty = t >> 5;

    // ---- load x tile (coalesced f4, swizzled store) ----
    const float4* xg = (const float4*)(x + (size_t)b * (NTOK * DIM));
    #pragma unroll
    for (int i = 0; i < 8; i++) {
        int idx = t + i * 256;
        int nn = idx >> 5, kk = idx & 31;
        ((float4*)xs)[SWZ(nn, kk)] = __ldg(xg + idx);
    }
    __syncthreads();

    // ---- fused q/k/v/q2/k2 GEMM: 640 cols in 10 chunks of 64 ----
    #pragma unroll 1
    for (int ch = 0; ch < 10; ch++) {
        #pragma unroll
        for (int i = 0; i < 8; i++) {              // stage 64x128 weight tile
            int idx = t + i * 256;
            int r = idx >> 5, kk = idx & 31;
            int cg = ch * 64 + r;
            const float4* srcp = (cg < 384) ? ((const float4*)(Wqkv + cg * DIM) + kk)
                                            : ((const float4*)(Wqkv2 + (cg - 384) * DIM) + kk);
            ((float4*)wb)[SWZ(r, kk)] = __ldg(srcp);
        }
        __syncthreads();

        u64 acc[8][2];
        gemm64(xs, wb, tx, ty, acc);

        const int ten = ch >> 1;                   // 0:q 1:k 2:v 3:q2 4:k2
        float* dst = (ten == 0) ? qs : (ten == 1) ? ks : (ten == 2) ? vs
                   : (ten == 3) ? q2s : k2s;
        const float mult = (ten == 0 || ten == 3) ? QSCALE : 1.0f;
        const float* bsrc = (ten < 3) ? (bqkv + ten * 128) : (bqkv2 + (ten - 3) * 128);
        const int lbase = (ch & 1) * 64;
        #pragma unroll
        for (int j = 0; j < 2; j++) {
            int col = lbase + tx + 32 * j;
            float bias = __ldg(bsrc + col);
            #pragma unroll
            for (int i = 0; i < 8; i++) {
                int r = ty * 8 + i;
                dst[SWZ(r, col >> 2) * 4 + (col & 3)] = (sum2(acc[i][j]) + bias) * mult;
            }
        }
        __syncthreads();
    }

    // ---- differential attention ----
    const float lam = g_lam;
    const float* pbm = g_pbm + (size_t)(b % NWIN) * (NH * NTOK * NTOK);
    const int n = t >> 2, qd = t & 3;      // 4 lanes per token row
    const ulonglong2* qu  = (const ulonglong2*)qs;
    const ulonglong2* q2u = (const ulonglong2*)q2s;
    const ulonglong2* ku  = (const ulonglong2*)ks;
    const ulonglong2* k2u = (const ulonglong2*)k2s;
    const ulonglong2* vu  = (const ulonglong2*)vs;

    #pragma unroll 1
    for (int h = 0; h < NH; h++) {
        const int ho4 = h * 8;   // f4-unit offset of head slice

        ulonglong2 qv[8], q2v[8];
        #pragma unroll
        for (int i = 0; i < 8; i++) {
            int g = (ho4 + i) ^ (n & 31);
            qv[i]  = qu [n * 32 + g];
            q2v[i] = q2u[n * 32 + g];
        }

        float lg[16];
        #pragma unroll 2
        for (int j = 0; j < 16; j++) {
            int m = qd + 4 * j;
            u64 a = 0ull, a2 = 0ull;
            #pragma unroll
            for (int i = 0; i < 8; i++) {
                int g = (ho4 + i) ^ (m & 31);
                ulonglong2 kv  = ku [m * 32 + g];
                ulonglong2 kv2 = k2u[m * 32 + g];
                ffma2(a,  qv[i].x,  kv.x);  ffma2(a,  qv[i].y,  kv.y);
                ffma2(a2, q2v[i].x, kv2.x); ffma2(a2, q2v[i].y, kv2.y);
            }
            lg[j] = sum2(a) - lam * sum2(a2) + __ldg(pbm + h * 4096 + n * 64 + m);
        }

        // softmax across row (4-lane cooperative)
        float M = lg[0];
        #pragma unroll
        for (int j = 1; j < 16; j++) M = fmaxf(M, lg[j]);
        M = fmaxf(M, __shfl_xor_sync(0xffffffffu, M, 1));
        M = fmaxf(M, __shfl_xor_sync(0xffffffffu, M, 2));
        float S = 0.f;
        #pragma unroll
        for (int j = 0; j < 16; j++) { lg[j] = __expf(lg[j] - M); S += lg[j]; }
        S += __shfl_xor_sync(0xffffffffu, S, 1);
        S += __shfl_xor_sync(0xffffffffu, S, 2);
        float inv = 1.0f / S;
        #pragma unroll
        for (int j = 0; j < 16; j++) att[n * 68 + qd + 4 * j] = lg[j] * inv;
        __syncthreads();

        // o = P @ V : thread owns head-dims [qd*8, qd*8+8) of its row, pairs over hd
        u64 o2[4] = {0ull, 0ull, 0ull, 0ull};
        #pragma unroll 4
        for (int jm = 0; jm < 16; jm++) {
            float4 p4 = *(const float4*)(att + n * 68 + jm * 4);
            #pragma unroll
            for (int mm = 0; mm < 4; mm++) {
                int m = jm * 4 + mm;
                float pv = (mm == 0) ? p4.x : (mm == 1) ? p4.y : (mm == 2) ? p4.z : p4.w;
                u64 pp = pack2(pv, pv);
                ulonglong2 v0 = vu[m * 32 + ((ho4 + qd * 2)     ^ (m & 31))];
                ulonglong2 v1 = vu[m * 32 + ((ho4 + qd * 2 + 1) ^ (m & 31))];
                ffma2(o2[0], pp, v0.x); ffma2(o2[1], pp, v0.y);
                ffma2(o2[2], pp, v1.x); ffma2(o2[3], pp, v1.y);
            }
        }

        // RMSNorm over head_dim + subln weight + (1 - lambda_init)
        u64 sq = 0ull;
        #pragma unroll
        for (int p = 0; p < 4; p++) ffma2(sq, o2[p], o2[p]);
        float ss = sum2(sq);
        ss += __shfl_xor_sync(0xffffffffu, ss, 1);
        ss += __shfl_xor_sync(0xffffffffu, ss, 2);
        float rs = rsqrtf(ss * (1.0f / 32.0f) + 1e-9f) * OUTS;

        float4 s0 = __ldg((const float4*)subln_w + qd * 2);
        float4 s1 = __ldg((const float4*)subln_w + qd * 2 + 1);
        float4 r0, r1;
        r0.x = lo2(o2[0]) * rs * s0.x;  r0.y = hi2(o2[0]) * rs * s0.y;
        r0.z = lo2(o2[1]) * rs * s0.z;  r0.w = hi2(o2[1]) * rs * s0.w;
        r1.x = lo2(o2[2]) * rs * s1.x;  r1.y = hi2(o2[2]) * rs * s1.y;
        r1.z = lo2(o2[3]) * rs * s1.z;  r1.w = hi2(o2[3]) * rs * s1.w;
        ((float4*)os)[SWZ(n, ho4 + qd * 2)]     = r0;
        ((float4*)os)[SWZ(n, ho4 + qd * 2 + 1)] = r1;
        __syncthreads();   // att dead for next head; os writes complete
    }

    // ---- output projection: 128 cols in 2 chunks of 64 ----
    #pragma unroll 1
    for (int ch = 0; ch < 2; ch++) {
        #pragma unroll
        for (int i = 0; i < 8; i++) {
            int idx = t + i * 256;
            int r = idx >> 5, kk = idx & 31;
            ((float4*)wb)[SWZ(r, kk)] = __ldg((const float4*)(Wproj + (ch * 64 + r) * DIM) + kk);
        }
        __syncthreads();

        u64 acc[8][2];
        gemm64(os, wb, tx, ty, acc);

        #pragma unroll
        for (int j = 0; j < 2; j++) {
            int col = ch * 64 + tx + 32 * j;
            #pragma unroll
            for (int i = 0; i < 8; i++) {
                int r = ty * 8 + i;
                qs[SWZ(r, col >> 2) * 4 + (col & 3)] = sum2(acc[i][j]);
            }
        }
        __syncthreads();
    }

    // ---- coalesced write-out with bias ----
    float* og = out + (size_t)b * (NTOK * DIM);
    #pragma unroll
    for (int i = 0; i < 32; i++) {
        int idx = t + i * 256;
        int nn = idx >> 7, c = idx & 127;
        og[idx] = qs[SWZ(nn, c >> 2) * 4 + (c & 3)] + __ldg(bproj + c);
    }
}

// ---------------------------------------------------------------------------
extern "C" void kernel_launch(void* const* d_in, const int* in_sizes, int n_in,
                              void* d_out, int out_size)
{
    const float* x      = (const float*)d_in[0];
    const float* mask   = (const float*)d_in[1];
    const float* Wqkv   = (const float*)d_in[2];
    const float* bqkv   = (const float*)d_in[3];
    const float* Wqkv2  = (const float*)d_in[4];
    const float* bqkv2  = (const float*)d_in[5];
    const float* Wp1    = (const float*)d_in[6];
    const float* bp1    = (const float*)d_in[7];
    const float* Wp2    = (const float*)d_in[8];
    const float* bp2    = (const float*)d_in[9];
    const float* lq1    = (const float*)d_in[10];
    const float* lk1    = (const float*)d_in[11];
    const float* lq2    = (const float*)d_in[12];
    const float* lk2    = (const float*)d_in[13];
    const float* subln  = (const float*)d_in[14];
    const float* Wproj  = (const float*)d_in[15];
    const float* bproj  = (const float*)d_in[16];
    float* out = (float*)d_out;

    const int SMEM = 57344 * (int)sizeof(float);   // 229376 B
    cudaFuncSetAttribute(wattn_kernel, cudaFuncAttributeMaxDynamicSharedMemorySize, SMEM);

    prep1_kernel<<<16, 256>>>(Wp1, bp1, Wp2, bp2, lq1, lk1, lq2, lk2);
    prep2_kernel<<<(NWIN * NH * NTOK * NTOK) / 256, 256>>>(mask);
    wattn_kernel<<<B_TOT, 256, SMEM>>>(x, Wqkv, bqkv, Wqkv2, bqkv2,
                                       subln, Wproj, bproj, out);
}

// round 5
// speedup vs baseline: 1.1836x; 1.0677x over previous
#include <cuda_runtime.h>
#include <math.h>

typedef unsigned long long u64;

#define B_TOT 3072
#define NTOK  64
#define DIM   128
#define NH    4
#define HD    32
#define NWIN  192
#define NTHR  512
#define QSCALE 0.1767766952966369f   // 32^-0.5
#define OUTS   0.8f                  // 1 - lambda_init

// ---------------- packed f32x2 helpers ----------------
__device__ __forceinline__ void ffma2(u64& d, u64 a, u64 b) {
    asm("fma.rn.f32x2 %0, %1, %2, %0;" : "+l"(d) : "l"(a), "l"(b));
}
__device__ __forceinline__ u64 pack2(float x, float y) {
    u64 r; asm("mov.b64 %0, {%1, %2};" : "=l"(r) : "f"(x), "f"(y)); return r;
}
__device__ __forceinline__ float lo2(u64 u) { return __uint_as_float((unsigned)u); }
__device__ __forceinline__ float hi2(u64 u) { return __uint_as_float((unsigned)(u >> 32)); }
__device__ __forceinline__ float sum2(u64 u) { return lo2(u) + hi2(u); }

// swizzled f4-unit index inside a [64 rows][32 f4] tile (conflict-free for all
// access patterns used below; stride 128 floats, zero padding)
__device__ __forceinline__ int SWZ(int row, int g) { return row * 32 + (g ^ (row & 31)); }

__device__ float g_pb[NH * NTOK * NTOK];
__device__ float g_pbm[NWIN * NH * NTOK * NTOK];   // mask + pos-bias, folded
__device__ float g_lam;

// ---------------------------------------------------------------------------
// Prep 1: polar-MLP relative-position bias table + lambda
// ---------------------------------------------------------------------------
__global__ void prep1_kernel(const float* __restrict__ Wp1, const float* __restrict__ bp1,
                             const float* __restrict__ Wp2, const float* __restrict__ bp2,
                             const float* __restrict__ lq1, const float* __restrict__ lk1,
                             const float* __restrict__ lq2, const float* __restrict__ lk2)
{
    int idx = blockIdx.x * blockDim.x + threadIdx.x;   // 0..4095 (n*64+m)
    if (idx < NTOK * NTOK) {
        int i = idx >> 6, j = idx & 63;
        float dx = (float)(i & 7) - (float)(j & 7);
        float dy = -((float)(i >> 3) - (float)(j >> 3));
        float r  = sqrtf(dx * dx + dy * dy + 1e-9f);
        float th = atan2f(dx, dy);
        float p0 = r * 0.10101525445522107f;                               // / sqrt(98)
        float p1 = (th + 3.14159265358979323846f) * 0.15915494309189535f;  // /(2pi)
        float o0 = __ldg(bp2 + 0), o1 = __ldg(bp2 + 1), o2 = __ldg(bp2 + 2), o3 = __ldg(bp2 + 3);
        for (int jj = 0; jj < 64; jj++) {
            float hv = fmaf(p0, __ldg(Wp1 + jj * 2), fmaf(p1, __ldg(Wp1 + jj * 2 + 1), __ldg(bp1 + jj)));
            float g  = 0.5f * hv * (1.0f + erff(hv * 0.7071067811865476f));   // exact GELU
            o0 = fmaf(g, __ldg(Wp2 +       jj), o0);
            o1 = fmaf(g, __ldg(Wp2 +  64 + jj), o1);
            o2 = fmaf(g, __ldg(Wp2 + 128 + jj), o2);
            o3 = fmaf(g, __ldg(Wp2 + 192 + jj), o3);
        }
        g_pb[          idx] = o0;
        g_pb[ 4096 +   idx] = o1;
        g_pb[ 8192 +   idx] = o2;
        g_pb[12288 +   idx] = o3;
    }
    if (idx == 0) {
        float s1 = 0.f, s2 = 0.f;
        for (int k = 0; k < 16; k++) {
            s1 = fmaf(__ldg(lq1 + k), __ldg(lk1 + k), s1);
            s2 = fmaf(__ldg(lq2 + k), __ldg(lk2 + k), s2);
        }
        g_lam = expf(s1) - expf(s2) + 0.2f;   // lambda_init = 0.2 (layer 0)
    }
}

// Prep 2: fold window mask into the bias table: pbm[w][h][n*64+m]
__global__ void prep2_kernel(const float* __restrict__ mask)
{
    int idx = blockIdx.x * 256 + threadIdx.x;          // 0 .. 3145727
    int rest = idx & 16383;                            // h*4096 + nm
    int w    = idx >> 14;
    int nm   = idx & 4095;
    g_pbm[idx] = g_pb[rest] + __ldg(mask + w * 4096 + nm);
}

// ---------------------------------------------------------------------------
// 64x64x128 register-blocked GEMM piece: src[64][128] @ w[64 cols][128]
// 512 threads: thread (tx,ty): rows ty*4..ty*4+3, cols {tx, tx+32}
// ---------------------------------------------------------------------------
__device__ __forceinline__ void gemm64(const float* __restrict__ src,
                                       const float* __restrict__ wsm,
                                       int tx, int ty, u64 acc[4][2])
{
    const ulonglong2* s = (const ulonglong2*)src;
    const ulonglong2* w = (const ulonglong2*)wsm;
    #pragma unroll
    for (int i = 0; i < 4; i++) { acc[i][0] = 0ull; acc[i][1] = 0ull; }
    #pragma unroll 4
    for (int kk = 0; kk < 32; kk++) {
        ulonglong2 w0 = w[tx * 32 + (kk ^ tx)];            // col tx
        ulonglong2 w1 = w[(tx + 32) * 32 + (kk ^ tx)];     // col tx+32 ((tx+32)&31==tx)
        #pragma unroll
        for (int i = 0; i < 4; i++) {
            int r = ty * 4 + i;
            ulonglong2 xv = s[r * 32 + (kk ^ (r & 31))];   // broadcast across warp
            ffma2(acc[i][0], xv.x, w0.x);
            ffma2(acc[i][0], xv.y, w0.y);
            ffma2(acc[i][1], xv.x, w1.x);
            ffma2(acc[i][1], xv.y, w1.y);
        }
    }
}

// ---------------------------------------------------------------------------
// Main fused kernel: one CTA per window, 512 threads.
// smem (floats, all [64][128] XOR-swizzled, no padding):
//   xs @0 (reused as os), qs @8192 (reused as proj staging), ks @16384,
//   vs @24576, q2s @32768, k2s @40960, wb @49152 (weights / att[64][68])
// total 57344 floats = 229376 B
// ---------------------------------------------------------------------------
__global__ __launch_bounds__(NTHR) void wattn_kernel(
    const float* __restrict__ x,
    const float* __restrict__ Wqkv,  const float* __restrict__ bqkv,
    const float* __restrict__ Wqkv2, const float* __restrict__ bqkv2,
    const float* __restrict__ subln_w,
    const float* __restrict__ Wproj, const float* __restrict__ bproj,
    float* __restrict__ out)
{
    extern __shared__ float sm[];
    float* xs  = sm;
    float* qs  = sm + 8192;
    float* ks  = sm + 16384;
    float* vs  = sm + 24576;
    float* q2s = sm + 32768;
    float* k2s = sm + 40960;
    float* wb  = sm + 49152;
    float* att = wb;
    float* os  = xs;

    const int b = blockIdx.x;
    const int t = threadIdx.x;
    const int tx = t & 31, ty = t >> 5;

    // ---- load x tile (coalesced f4, swizzled store) ----
    const float4* xg = (const float4*)(x + (size_t)b * (NTOK * DIM));
    #pragma unroll
    for (int i = 0; i < 4; i++) {
        int idx = t + i * NTHR;
        int nn = idx >> 5, kk = idx & 31;
        ((float4*)xs)[SWZ(nn, kk)] = __ldg(xg + idx);
    }
    __syncthreads();

    // ---- fused q/k/v/q2/k2 GEMM: 640 cols in 10 chunks of 64 ----
    #pragma unroll 1
    for (int ch = 0; ch < 10; ch++) {
        #pragma unroll
        for (int i = 0; i < 4; i++) {              // stage 64x128 weight tile
            int idx = t + i * NTHR;
            int r = idx >> 5, kk = idx & 31;
            int cg = ch * 64 + r;
            const float4* srcp = (cg < 384) ? ((const float4*)(Wqkv + cg * DIM) + kk)
                                            : ((const float4*)(Wqkv2 + (cg - 384) * DIM) + kk);
            ((float4*)wb)[SWZ(r, kk)] = __ldg(srcp);
        }
        __syncthreads();

        u64 acc[4][2];
        gemm64(xs, wb, tx, ty, acc);

        const int ten = ch >> 1;                   // 0:q 1:k 2:v 3:q2 4:k2
        float* dst = (ten == 0) ? qs : (ten == 1) ? ks : (ten == 2) ? vs
                   : (ten == 3) ? q2s : k2s;
        const float mult = (ten == 0 || ten == 3) ? QSCALE : 1.0f;
        const float* bsrc = (ten < 3) ? (bqkv + ten * 128) : (bqkv2 + (ten - 3) * 128);
        const int lbase = (ch & 1) * 64;
        #pragma unroll
        for (int j = 0; j < 2; j++) {
            int col = lbase + tx + 32 * j;
            float bias = __ldg(bsrc + col);
            #pragma unroll
            for (int i = 0; i < 4; i++) {
                int r = ty * 4 + i;
                dst[SWZ(r, col >> 2) * 4 + (col & 3)] = (sum2(acc[i][j]) + bias) * mult;
            }
        }
        __syncthreads();
    }

    // ---- differential attention: 8 lanes per token row ----
    const float lam = g_lam;
    const float* pbm = g_pbm + (size_t)(b % NWIN) * (NH * NTOK * NTOK);
    const int n = t >> 3, qd = t & 7;
    const ulonglong2* qu  = (const ulonglong2*)qs;
    const ulonglong2* q2u = (const ulonglong2*)q2s;
    const ulonglong2* ku  = (const ulonglong2*)ks;
    const ulonglong2* k2u = (const ulonglong2*)k2s;
    const ulonglong2* vu  = (const ulonglong2*)vs;

    #pragma unroll 1
    for (int h = 0; h < NH; h++) {
        const int ho4 = h * 8;   // f4-unit offset of head slice

        ulonglong2 qv[8], q2v[8];
        #pragma unroll
        for (int i = 0; i < 8; i++) {
            int g = (ho4 + i) ^ (n & 31);
            qv[i]  = qu [n * 32 + g];
            q2v[i] = q2u[n * 32 + g];
        }

        float lg[8];
        #pragma unroll 2
        for (int j = 0; j < 8; j++) {
            int m = qd + 8 * j;
            u64 a = 0ull, a2 = 0ull;
            #pragma unroll
            for (int i = 0; i < 8; i++) {
                int g = (ho4 + i) ^ (m & 31);       // bank = i^qd across lanes: conflict-free
                ulonglong2 kv  = ku [m * 32 + g];
                ulonglong2 kv2 = k2u[m * 32 + g];
                ffma2(a,  qv[i].x,  kv.x);  ffma2(a,  qv[i].y,  kv.y);
                ffma2(a2, q2v[i].x, kv2.x); ffma2(a2, q2v[i].y, kv2.y);
            }
            lg[j] = sum2(a) - lam * sum2(a2) + __ldg(pbm + h * 4096 + n * 64 + m);
        }

        // softmax across row (8-lane cooperative)
        float M = lg[0];
        #pragma unroll
        for (int j = 1; j < 8; j++) M = fmaxf(M, lg[j]);
        M = fmaxf(M, __shfl_xor_sync(0xffffffffu, M, 1));
        M = fmaxf(M, __shfl_xor_sync(0xffffffffu, M, 2));
        M = fmaxf(M, __shfl_xor_sync(0xffffffffu, M, 4));
        float S = 0.f;
        #pragma unroll
        for (int j = 0; j < 8; j++) { lg[j] = __expf(lg[j] - M); S += lg[j]; }
        S += __shfl_xor_sync(0xffffffffu, S, 1);
        S += __shfl_xor_sync(0xffffffffu, S, 2);
        S += __shfl_xor_sync(0xffffffffu, S, 4);
        float inv = 1.0f / S;
        #pragma unroll
        for (int j = 0; j < 8; j++) att[n * 68 + qd + 8 * j] = lg[j] * inv;
        __syncthreads();

        // o = P @ V : lane owns head-dims [qd*4, qd*4+4) of its row
        u64 o2[2] = {0ull, 0ull};
        const int gv = ho4 + qd;
        #pragma unroll 4
        for (int jm = 0; jm < 16; jm++) {
            float4 p4 = *(const float4*)(att + n * 68 + jm * 4);
            #pragma unroll
            for (int mm = 0; mm < 4; mm++) {
                int m = jm * 4 + mm;
                float pv = (mm == 0) ? p4.x : (mm == 1) ? p4.y : (mm == 2) ? p4.z : p4.w;
                u64 pp = pack2(pv, pv);
                ulonglong2 v0 = vu[m * 32 + (gv ^ (m & 31))];
                ffma2(o2[0], pp, v0.x); ffma2(o2[1], pp, v0.y);
            }
        }

        // RMSNorm over head_dim + subln weight + (1 - lambda_init)
        u64 sq = 0ull;
        ffma2(sq, o2[0], o2[0]);
        ffma2(sq, o2[1], o2[1]);
        float ss = sum2(sq);
        ss += __shfl_xor_sync(0xffffffffu, ss, 1);
        ss += __shfl_xor_sync(0xffffffffu, ss, 2);
        ss += __shfl_xor_sync(0xffffffffu, ss, 4);
        float rs = rsqrtf(ss * (1.0f / 32.0f) + 1e-9f) * OUTS;

        float4 sW = __ldg((const float4*)subln_w + qd);
        float4 r0;
        r0.x = lo2(o2[0]) * rs * sW.x;  r0.y = hi2(o2[0]) * rs * sW.y;
        r0.z = lo2(o2[1]) * rs * sW.z;  r0.w = hi2(o2[1]) * rs * sW.w;
        ((float4*)os)[SWZ(n, gv)] = r0;
        __syncthreads();   // att dead for next head; os writes complete
    }

    // ---- output projection: 128 cols in 2 chunks of 64 ----
    #pragma unroll 1
    for (int ch = 0; ch < 2; ch++) {
        #pragma unroll
        for (int i = 0; i < 4; i++) {
            int idx = t + i * NTHR;
            int r = idx >> 5, kk = idx & 31;
            ((float4*)wb)[SWZ(r, kk)] = __ldg((const float4*)(Wproj + (ch * 64 + r) * DIM) + kk);
        }
        __syncthreads();

        u64 acc[4][2];
        gemm64(os, wb, tx, ty, acc);

        #pragma unroll
        for (int j = 0; j < 2; j++) {
            int col = ch * 64 + tx + 32 * j;
            #pragma unroll
            for (int i = 0; i < 4; i++) {
                int r = ty * 4 + i;
                qs[SWZ(r, col >> 2) * 4 + (col & 3)] = sum2(acc[i][j]);
            }
        }
        __syncthreads();
    }

    // ---- coalesced write-out with bias ----
    float* og = out + (size_t)b * (NTOK * DIM);
    #pragma unroll
    for (int i = 0; i < 16; i++) {
        int idx = t + i * NTHR;
        int nn = idx >> 7, c = idx & 127;
        og[idx] = qs[SWZ(nn, c >> 2) * 4 + (c & 3)] + __ldg(bproj + c);
    }
}

// ---------------------------------------------------------------------------
extern "C" void kernel_launch(void* const* d_in, const int* in_sizes, int n_in,
                              void* d_out, int out_size)
{
    const float* x      = (const float*)d_in[0];
    const float* mask   = (const float*)d_in[1];
    const float* Wqkv   = (const float*)d_in[2];
    const float* bqkv   = (const float*)d_in[3];
    const float* Wqkv2  = (const float*)d_in[4];
    const float* bqkv2  = (const float*)d_in[5];
    const float* Wp1    = (const float*)d_in[6];
    const float* bp1    = (const float*)d_in[7];
    const float* Wp2    = (const float*)d_in[8];
    const float* bp2    = (const float*)d_in[9];
    const float* lq1    = (const float*)d_in[10];
    const float* lk1    = (const float*)d_in[11];
    const float* lq2    = (const float*)d_in[12];
    const float* lk2    = (const float*)d_in[13];
    const float* subln  = (const float*)d_in[14];
    const float* Wproj  = (const float*)d_in[15];
    const float* bproj  = (const float*)d_in[16];
    float* out = (float*)d_out;

    const int SMEM = 57344 * (int)sizeof(float);   // 229376 B
    cudaFuncSetAttribute(wattn_kernel, cudaFuncAttributeMaxDynamicSharedMemorySize, SMEM);

    prep1_kernel<<<16, 256>>>(Wp1, bp1, Wp2, bp2, lq1, lk1, lq2, lk2);
    prep2_kernel<<<(NWIN * NH * NTOK * NTOK) / 256, 256>>>(mask);
    wattn_kernel<<<B_TOT, NTHR, SMEM>>>(x, Wqkv, bqkv, Wqkv2, bqkv2,
                                        subln, Wproj, bproj, out);
}

// round 7
// speedup vs baseline: 1.9866x; 1.6785x over previous
#include <cuda_runtime.h>
#include <cuda_bf16.h>
#include <math.h>

typedef unsigned long long u64;
typedef unsigned int u32;

#define B_TOT 3072
#define NTOK  64
#define DIM   128
#define NH    4
#define NWIN  192
#define NTHR  512
#define QSCALE 0.1767766952966369f   // 32^-0.5
#define OUTS   0.8f                  // 1 - lambda_init

// ---------------- packed f32x2 helpers (attention) ----------------
__device__ __forceinline__ void ffma2(u64& d, u64 a, u64 b) {
    asm("fma.rn.f32x2 %0, %1, %2, %0;" : "+l"(d) : "l"(a), "l"(b));
}
__device__ __forceinline__ u64 pack2(float x, float y) {
    u64 r; asm("mov.b64 %0, {%1, %2};" : "=l"(r) : "f"(x), "f"(y)); return r;
}
__device__ __forceinline__ float lo2(u64 u) { return __uint_as_float((unsigned)u); }
__device__ __forceinline__ float hi2(u64 u) { return __uint_as_float((unsigned)(u >> 32)); }
__device__ __forceinline__ float sum2(u64 u) { return lo2(u) + hi2(u); }

// fp32 tile swizzle: f4-unit index in [64 rows][32 f4]
__device__ __forceinline__ int SWZ(int row, int g) { return row * 32 + (g ^ (row & 31)); }
// bf16 image swizzle: byte offset in [64 rows][256B rows], 16B-unit XOR -> ldmatrix conflict-free
__device__ __forceinline__ int BSW(int r, int byte) {
    return r * 256 + ((((byte >> 4) ^ r) & 15) << 4) + (byte & 15);
}

// ---------------- mma.sync helpers (portable sm_80+ ISA) ----------------
__device__ __forceinline__ u32 sptr(const void* p) { return (u32)__cvta_generic_to_shared(p); }
__device__ __forceinline__ void ldsm4(u32 r[4], u32 addr) {
    asm volatile("ldmatrix.sync.aligned.m8n8.x4.shared.b16 {%0,%1,%2,%3}, [%4];"
                 : "=r"(r[0]), "=r"(r[1]), "=r"(r[2]), "=r"(r[3]) : "r"(addr));
}
__device__ __forceinline__ void ldsm2(u32 r[2], u32 addr) {
    asm volatile("ldmatrix.sync.aligned.m8n8.x2.shared.b16 {%0,%1}, [%2];"
                 : "=r"(r[0]), "=r"(r[1]) : "r"(addr));
}
__device__ __forceinline__ void mma16816(float d[4], const u32 a[4], const u32 b[2]) {
    asm volatile("mma.sync.aligned.m16n8k16.row.col.f32.bf16.bf16.f32 "
                 "{%0,%1,%2,%3}, {%4,%5,%6,%7}, {%8,%9}, {%0,%1,%2,%3};"
                 : "+f"(d[0]), "+f"(d[1]), "+f"(d[2]), "+f"(d[3])
                 : "r"(a[0]), "r"(a[1]), "r"(a[2]), "r"(a[3]), "r"(b[0]), "r"(b[1]));
}
__device__ __forceinline__ unsigned short bfbits(__nv_bfloat16 h) {
    return *reinterpret_cast<unsigned short*>(&h);
}

__device__ float g_pb[NH * NTOK * NTOK];
__device__ float g_pbm[NWIN * NH * NTOK * NTOK];
__device__ float g_lam;
// 12 chunks (q0,q1,k0,k1,v0,v1,q20,q21,k20,k21,p0,p1) x (hi image 16KB + lo image 16KB)
__device__ __nv_bfloat16 g_w[12 * 16384];

// ---------------------------------------------------------------------------
// Prep 1: polar-MLP bias table + lambda
// ---------------------------------------------------------------------------
__global__ void prep1_kernel(const float* __restrict__ Wp1, const float* __restrict__ bp1,
                             const float* __restrict__ Wp2, const float* __restrict__ bp2,
                             const float* __restrict__ lq1, const float* __restrict__ lk1,
                             const float* __restrict__ lq2, const float* __restrict__ lk2)
{
    int idx = blockIdx.x * blockDim.x + threadIdx.x;
    if (idx < NTOK * NTOK) {
        int i = idx >> 6, j = idx & 63;
        float dx = (float)(i & 7) - (float)(j & 7);
        float dy = -((float)(i >> 3) - (float)(j >> 3));
        float r  = sqrtf(dx * dx + dy * dy + 1e-9f);
        float th = atan2f(dx, dy);
        float p0 = r * 0.10101525445522107f;
        float p1 = (th + 3.14159265358979323846f) * 0.15915494309189535f;
        float o0 = __ldg(bp2 + 0), o1 = __ldg(bp2 + 1), o2 = __ldg(bp2 + 2), o3 = __ldg(bp2 + 3);
        for (int jj = 0; jj < 64; jj++) {
            float hv = fmaf(p0, __ldg(Wp1 + jj * 2), fmaf(p1, __ldg(Wp1 + jj * 2 + 1), __ldg(bp1 + jj)));
            float g  = 0.5f * hv * (1.0f + erff(hv * 0.7071067811865476f));
            o0 = fmaf(g, __ldg(Wp2 +       jj), o0);
            o1 = fmaf(g, __ldg(Wp2 +  64 + jj), o1);
            o2 = fmaf(g, __ldg(Wp2 + 128 + jj), o2);
            o3 = fmaf(g, __ldg(Wp2 + 192 + jj), o3);
        }
        g_pb[          idx] = o0;
        g_pb[ 4096 +   idx] = o1;
        g_pb[ 8192 +   idx] = o2;
        g_pb[12288 +   idx] = o3;
    }
    if (idx == 0) {
        float s1 = 0.f, s2 = 0.f;
        for (int k = 0; k < 16; k++) {
            s1 = fmaf(__ldg(lq1 + k), __ldg(lk1 + k), s1);
            s2 = fmaf(__ldg(lq2 + k), __ldg(lk2 + k), s2);
        }
        g_lam = expf(s1) - expf(s2) + 0.2f;
    }
}

__global__ void prep2_kernel(const float* __restrict__ mask)
{
    int idx = blockIdx.x * 256 + threadIdx.x;
    int rest = idx & 16383;
    int w    = idx >> 14;
    int nm   = idx & 4095;
    g_pbm[idx] = g_pb[rest] + __ldg(mask + w * 4096 + nm);
}

// Prep 3: bf16 hi/lo split of weights into swizzled ldmatrix images
__global__ void prepw_kernel(const float* __restrict__ Wqkv,
                             const float* __restrict__ Wqkv2,
                             const float* __restrict__ Wproj)
{
    int idx = blockIdx.x * 256 + threadIdx.x;   // 0..98303
    int c   = idx >> 13;                        // chunk 0..11 (8192 elems each)
    int rem = idx & 8191;
    int r = rem >> 7, k = rem & 127;            // r = col-in-chunk, k
    int cg = c * 64 + r;
    float v;
    if (cg < 384)      v = __ldg(Wqkv  + cg * 128 + k);
    else if (cg < 640) v = __ldg(Wqkv2 + (cg - 384) * 128 + k);
    else               v = __ldg(Wproj + (cg - 640) * 128 + k);
    __nv_bfloat16 h = __float2bfloat16(v);
    __nv_bfloat16 l = __float2bfloat16(v - __bfloat162float(h));
    int e = (c * 32768 + BSW(r, k * 2)) >> 1;   // hi image element
    g_w[e] = h;
    g_w[e + 8192] = l;                          // lo image +16KB
}

// ---------------------------------------------------------------------------
// 64xN cols MMA GEMM piece over one 64-col weight chunk.
// A images at abase (hi) / abase+16384 (lo); B images at bbase / +16384.
// warp w: m-group mg = w&3 (tokens mg*16..+15), cols (w>>2)*16 + nt*8.
// ---------------------------------------------------------------------------
__device__ __forceinline__ void mma_chunk(u32 abase, u32 bbase, int mg, int wg, int lid,
                                          float d[2][4])
{
    #pragma unroll
    for (int nt = 0; nt < 2; nt++)
        #pragma unroll
        for (int i = 0; i < 4; i++) d[nt][i] = 0.f;
    const int ar = mg * 16 + (lid & 15);
    const int ak = (lid & 16);
    const int bc = wg * 16 + (lid & 7);
    const int bk = (lid & 8) << 1;
    #pragma unroll
    for (int ks = 0; ks < 8; ks++) {
        u32 ah[4], al[4];
        u32 aaddr = abase + BSW(ar, ks * 32 + ak);
        ldsm4(ah, aaddr);
        ldsm4(al, aaddr + 16384);
        #pragma unroll
        for (int nt = 0; nt < 2; nt++) {
            u32 bh[2], bl[2];
            u32 baddr = bbase + BSW(bc + nt * 8, ks * 32 + bk);
            ldsm2(bh, baddr);
            ldsm2(bl, baddr + 16384);
            mma16816(d[nt], ah, bh);
            mma16816(d[nt], ah, bl);
            mma16816(d[nt], al, bh);
        }
    }
}

// ---------------------------------------------------------------------------
// Main fused kernel, 512 threads. smem bytes (total 229376):
//   A [0,32768):      x bf16 hi/lo images (16KB each)  -> later os fp32 (SWZ)
//   B [32768,65536):  W staging hi/lo                  -> att scratch -> os images
//   C [65536,229376): qs,ks,vs,q2s,k2s fp32 SWZ tiles (5 x 32KB); qs reused for proj W
// ---------------------------------------------------------------------------
__global__ __launch_bounds__(NTHR) void wattn_kernel(
    const float* __restrict__ x,
    const float* __restrict__ bqkv, const float* __restrict__ bqkv2,
    const float* __restrict__ subln_w, const float* __restrict__ bproj,
    float* __restrict__ out)
{
    extern __shared__ float sm[];
    char* smc = (char*)sm;
    float* os  = sm;                  // region A (after QKV)
    float* att = sm + 8192;           // region B (during attention)
    float* qs  = sm + 16384;          // region C
    float* ks  = sm + 24576;
    float* vs  = sm + 32768;
    float* q2s = sm + 40960;
    float* k2s = sm + 49152;

    const int b = blockIdx.x;
    const int t = threadIdx.x;
    const int w = t >> 5, lid = t & 31;
    const int mg = w & 3, wg = w >> 2;
    const u32 smb = sptr(sm);

    // ---- load x, split to bf16 hi/lo swizzled images (region A) ----
    const float4* xg = (const float4*)(x + (size_t)b * (NTOK * DIM));
    #pragma unroll
    for (int i = 0; i < 4; i++) {
        int idx = t + i * NTHR;                   // 2048 float4s
        int token = idx >> 5, kb = idx & 31;      // kb: f4 group
        float4 v = __ldg(xg + idx);
        __nv_bfloat16 h0 = __float2bfloat16(v.x), h1 = __float2bfloat16(v.y);
        __nv_bfloat16 h2 = __float2bfloat16(v.z), h3 = __float2bfloat16(v.w);
        __nv_bfloat16 l0 = __float2bfloat16(v.x - __bfloat162float(h0));
        __nv_bfloat16 l1 = __float2bfloat16(v.y - __bfloat162float(h1));
        __nv_bfloat16 l2 = __float2bfloat16(v.z - __bfloat162float(h2));
        __nv_bfloat16 l3 = __float2bfloat16(v.w - __bfloat162float(h3));
        u64 hp = (u64)bfbits(h0) | ((u64)bfbits(h1) << 16) | ((u64)bfbits(h2) << 32) | ((u64)bfbits(h3) << 48);
        u64 lp = (u64)bfbits(l0) | ((u64)bfbits(l1) << 16) | ((u64)bfbits(l2) << 32) | ((u64)bfbits(l3) << 48);
        int sw = BSW(token, kb * 8);
        *(u64*)(smc + sw)         = hp;
        *(u64*)(smc + 16384 + sw) = lp;
    }
    __syncthreads();

    // ---- QKV: 10 chunks of 64 cols via mma.sync ----
    #pragma unroll 1
    for (int ch = 0; ch < 10; ch++) {
        const uint4* src = (const uint4*)((const char*)g_w + ch * 32768);
        uint4* dstp = (uint4*)(smc + 32768);
        #pragma unroll
        for (int i = 0; i < 4; i++) dstp[t + i * NTHR] = __ldg(src + t + i * NTHR);
        __syncthreads();

        float d[2][4];
        mma_chunk(smb, smb + 32768, mg, wg, lid, d);

        const int ten = ch >> 1;                  // 0:q 1:k 2:v 3:q2 4:k2
        float* dst = (ten == 0) ? qs : (ten == 1) ? ks : (ten == 2) ? vs
                   : (ten == 3) ? q2s : k2s;
        const float mult = (ten == 0 || ten == 3) ? QSCALE : 1.0f;
        const float* bsrc = (ten < 3) ? (bqkv + ten * 128) : (bqkv2 + (ten - 3) * 128);
        const int r0 = mg * 16 + (lid >> 2);
        #pragma unroll
        for (int nt = 0; nt < 2; nt++) {
            int tc = (ch & 1) * 64 + wg * 16 + nt * 8 + 2 * (lid & 3);
            float b0 = __ldg(bsrc + tc), b1 = __ldg(bsrc + tc + 1);
            int g = tc >> 2, sub = tc & 3;
            float2 v01 = {(d[nt][0] + b0) * mult, (d[nt][1] + b1) * mult};
            float2 v23 = {(d[nt][2] + b0) * mult, (d[nt][3] + b1) * mult};
            *(float2*)(dst + SWZ(r0,     g) * 4 + sub) = v01;
            *(float2*)(dst + SWZ(r0 + 8, g) * 4 + sub) = v23;
        }
        __syncthreads();
    }

    // ---- differential attention (SIMT fp32, as round 5) ----
    const float lam = g_lam;
    const float* pbm = g_pbm + (size_t)(b % NWIN) * (NH * NTOK * NTOK);
    const int n = t >> 3, qd = t & 7;
    const ulonglong2* qu  = (const ulonglong2*)qs;
    const ulonglong2* q2u = (const ulonglong2*)q2s;
    const ulonglong2* ku  = (const ulonglong2*)ks;
    const ulonglong2* k2u = (const ulonglong2*)k2s;
    const ulonglong2* vu  = (const ulonglong2*)vs;

    #pragma unroll 1
    for (int h = 0; h < NH; h++) {
        const int ho4 = h * 8;
        ulonglong2 qv[8], q2v[8];
        #pragma unroll
        for (int i = 0; i < 8; i++) {
            int g = (ho4 + i) ^ (n & 31);
            qv[i]  = qu [n * 32 + g];
            q2v[i] = q2u[n * 32 + g];
        }
        float lg[8];
        #pragma unroll 2
        for (int j = 0; j < 8; j++) {
            int m = qd + 8 * j;
            u64 a = 0ull, a2 = 0ull;
            #pragma unroll
            for (int i = 0; i < 8; i++) {
                int g = (ho4 + i) ^ (m & 31);
                ulonglong2 kv  = ku [m * 32 + g];
                ulonglong2 kv2 = k2u[m * 32 + g];
                ffma2(a,  qv[i].x,  kv.x);  ffma2(a,  qv[i].y,  kv.y);
                ffma2(a2, q2v[i].x, kv2.x); ffma2(a2, q2v[i].y, kv2.y);
            }
            lg[j] = sum2(a) - lam * sum2(a2) + __ldg(pbm + h * 4096 + n * 64 + m);
        }
        float M = lg[0];
        #pragma unroll
        for (int j = 1; j < 8; j++) M = fmaxf(M, lg[j]);
        M = fmaxf(M, __shfl_xor_sync(0xffffffffu, M, 1));
        M = fmaxf(M, __shfl_xor_sync(0xffffffffu, M, 2));
        M = fmaxf(M, __shfl_xor_sync(0xffffffffu, M, 4));
        float S = 0.f;
        #pragma unroll
        for (int j = 0; j < 8; j++) { lg[j] = __expf(lg[j] - M); S += lg[j]; }
        S += __shfl_xor_sync(0xffffffffu, S, 1);
        S += __shfl_xor_sync(0xffffffffu, S, 2);
        S += __shfl_xor_sync(0xffffffffu, S, 4);
        float inv = 1.0f / S;
        #pragma unroll
        for (int j = 0; j < 8; j++) att[n * 68 + qd + 8 * j] = lg[j] * inv;
        __syncthreads();

        u64 o2[2] = {0ull, 0ull};
        const int gv = ho4 + qd;
        #pragma unroll 4
        for (int jm = 0; jm < 16; jm++) {
            float4 p4 = *(const float4*)(att + n * 68 + jm * 4);
            #pragma unroll
            for (int mm = 0; mm < 4; mm++) {
                int m = jm * 4 + mm;
                float pv = (mm == 0) ? p4.x : (mm == 1) ? p4.y : (mm == 2) ? p4.z : p4.w;
                u64 pp = pack2(pv, pv);
                ulonglong2 v0 = vu[m * 32 + (gv ^ (m & 31))];
                ffma2(o2[0], pp, v0.x); ffma2(o2[1], pp, v0.y);
            }
        }
        u64 sq = 0ull;
        ffma2(sq, o2[0], o2[0]);
        ffma2(sq, o2[1], o2[1]);
        float ss = sum2(sq);
        ss += __shfl_xor_sync(0xffffffffu, ss, 1);
        ss += __shfl_xor_sync(0xffffffffu, ss, 2);
        ss += __shfl_xor_sync(0xffffffffu, ss, 4);
        float rs = rsqrtf(ss * (1.0f / 32.0f) + 1e-9f) * OUTS;
        float4 sW = __ldg((const float4*)subln_w + qd);
        float4 r0;
        r0.x = lo2(o2[0]) * rs * sW.x;  r0.y = hi2(o2[0]) * rs * sW.y;
        r0.z = lo2(o2[1]) * rs * sW.z;  r0.w = hi2(o2[1]) * rs * sW.w;
        ((float4*)os)[SWZ(n, gv)] = r0;
        __syncthreads();
    }

    // ---- convert os -> bf16 hi/lo images in region B ----
    #pragma unroll
    for (int i = 0; i < 4; i++) {
        int idx = t + i * NTHR;
        int token = idx >> 5, g4 = idx & 31;
        float4 v = ((const float4*)os)[SWZ(token, g4)];
        __nv_bfloat16 h0 = __float2bfloat16(v.x), h1 = __float2bfloat16(v.y);
        __nv_bfloat16 h2 = __float2bfloat16(v.z), h3 = __float2bfloat16(v.w);
        __nv_bfloat16 l0 = __float2bfloat16(v.x - __bfloat162float(h0));
        __nv_bfloat16 l1 = __float2bfloat16(v.y - __bfloat162float(h1));
        __nv_bfloat16 l2 = __float2bfloat16(v.z - __bfloat162float(h2));
        __nv_bfloat16 l3 = __float2bfloat16(v.w - __bfloat162float(h3));
        u64 hp = (u64)bfbits(h0) | ((u64)bfbits(h1) << 16) | ((u64)bfbits(h2) << 32) | ((u64)bfbits(h3) << 48);
        u64 lp = (u64)bfbits(l0) | ((u64)bfbits(l1) << 16) | ((u64)bfbits(l2) << 32) | ((u64)bfbits(l3) << 48);
        int sw = BSW(token, g4 * 8);
        *(u64*)(smc + 32768 + sw) = hp;
        *(u64*)(smc + 49152 + sw) = lp;
    }

    // ---- proj: 2 chunks of 64 cols; W staged in (dead) qs region ----
    float* og = out + (size_t)b * (NTOK * DIM);
    #pragma unroll 1
    for (int pc = 0; pc < 2; pc++) {
        const uint4* src = (const uint4*)((const char*)g_w + (10 + pc) * 32768);
        uint4* dstp = (uint4*)(smc + 65536);
        #pragma unroll
        for (int i = 0; i < 4; i++) dstp[t + i * NTHR] = __ldg(src + t + i * NTHR);
        __syncthreads();

        float d[2][4];
        mma_chunk(smb + 32768, smb + 65536, mg, wg, lid, d);

        const int r0 = mg * 16 + (lid >> 2);
        #pragma unroll
        for (int nt = 0; nt < 2; nt++) {
            int cg = pc * 64 + wg * 16 + nt * 8 + 2 * (lid & 3);
            float b0 = __ldg(bproj + cg), b1 = __ldg(bproj + cg + 1);
            float2 v01 = {d[nt][0] + b0, d[nt][1] + b1};
            float2 v23 = {d[nt][2] + b0, d[nt][3] + b1};
            *(float2*)(og + r0 * 128 + cg)       = v01;
            *(float2*)(og + (r0 + 8) * 128 + cg) = v23;
        }
        __syncthreads();
    }
}

// ---------------------------------------------------------------------------
extern "C" void kernel_launch(void* const* d_in, const int* in_sizes, int n_in,
                              void* d_out, int out_size)
{
    const float* x      = (const float*)d_in[0];
    const float* mask   = (const float*)d_in[1];
    const float* Wqkv   = (const float*)d_in[2];
    const float* bqkv   = (const float*)d_in[3];
    const float* Wqkv2  = (const float*)d_in[4];
    const float* bqkv2  = (const float*)d_in[5];
    const float* Wp1    = (const float*)d_in[6];
    const float* bp1    = (const float*)d_in[7];
    const float* Wp2    = (const float*)d_in[8];
    const float* bp2    = (const float*)d_in[9];
    const float* lq1    = (const float*)d_in[10];
    const float* lk1    = (const float*)d_in[11];
    const float* lq2    = (const float*)d_in[12];
    const float* lk2    = (const float*)d_in[13];
    const float* subln  = (const float*)d_in[14];
    const float* Wproj  = (const float*)d_in[15];
    const float* bproj  = (const float*)d_in[16];
    float* out = (float*)d_out;

    const int SMEM = 229376;
    cudaFuncSetAttribute(wattn_kernel, cudaFuncAttributeMaxDynamicSharedMemorySize, SMEM);

    prep1_kernel<<<16, 256>>>(Wp1, bp1, Wp2, bp2, lq1, lk1, lq2, lk2);
    prep2_kernel<<<(NWIN * NH * NTOK * NTOK) / 256, 256>>>(mask);
    prepw_kernel<<<384, 256>>>(Wqkv, Wqkv2, Wproj);
    wattn_kernel<<<B_TOT, NTHR, SMEM>>>(x, bqkv, bqkv2, subln, bproj, out);
}

// round 9
// speedup vs baseline: 2.5608x; 1.2891x over previous
#include <cuda_runtime.h>
#include <cuda_bf16.h>
#include <math.h>

typedef unsigned long long u64;
typedef unsigned int u32;

#define B_TOT 3072
#define NTOK  64
#define DIM   128
#define NH    4
#define NWIN  192
#define NTHR  512
#define QSCALE 0.1767766952966369f   // 32^-0.5
#define OUTS   0.8f                  // 1 - lambda_init

// ---------------- packed f32x2 helpers (attention) ----------------
__device__ __forceinline__ void ffma2(u64& d, u64 a, u64 b) {
    asm("fma.rn.f32x2 %0, %1, %2, %0;" : "+l"(d) : "l"(a), "l"(b));
}
__device__ __forceinline__ u64 pack2(float x, float y) {
    u64 r; asm("mov.b64 %0, {%1, %2};" : "=l"(r) : "f"(x), "f"(y)); return r;
}
__device__ __forceinline__ float lo2(u64 u) { return __uint_as_float((unsigned)u); }
__device__ __forceinline__ float hi2(u64 u) { return __uint_as_float((unsigned)(u >> 32)); }

// fp32 tile swizzle: f4-unit index in [64 rows][32 f4]
__device__ __forceinline__ int SWZ(int row, int g) { return row * 32 + (g ^ (row & 31)); }
// bf16 image swizzle: byte offset in [64 rows][256B rows], 16B-unit XOR -> ldmatrix conflict-free
__device__ __forceinline__ int BSW(int r, int byte) {
    return r * 256 + ((((byte >> 4) ^ r) & 15) << 4) + (byte & 15);
}

// ---------------- mma.sync helpers (portable sm_80+ ISA) ----------------
__device__ __forceinline__ u32 sptr(const void* p) { return (u32)__cvta_generic_to_shared(p); }
__device__ __forceinline__ void ldsm4(u32 r[4], u32 addr) {
    asm volatile("ldmatrix.sync.aligned.m8n8.x4.shared.b16 {%0,%1,%2,%3}, [%4];"
                 : "=r"(r[0]), "=r"(r[1]), "=r"(r[2]), "=r"(r[3]) : "r"(addr));
}
__device__ __forceinline__ void ldsm2(u32 r[2], u32 addr) {
    asm volatile("ldmatrix.sync.aligned.m8n8.x2.shared.b16 {%0,%1}, [%2];"
                 : "=r"(r[0]), "=r"(r[1]) : "r"(addr));
}
__device__ __forceinline__ void mma16816(float d[4], const u32 a[4], const u32 b[2]) {
    asm volatile("mma.sync.aligned.m16n8k16.row.col.f32.bf16.bf16.f32 "
                 "{%0,%1,%2,%3}, {%4,%5,%6,%7}, {%8,%9}, {%0,%1,%2,%3};"
                 : "+f"(d[0]), "+f"(d[1]), "+f"(d[2]), "+f"(d[3])
                 : "r"(a[0]), "r"(a[1]), "r"(a[2]), "r"(a[3]), "r"(b[0]), "r"(b[1]));
}
__device__ __forceinline__ unsigned short bfbits(__nv_bfloat16 h) {
    return *reinterpret_cast<unsigned short*>(&h);
}

__device__ float g_pb[NH * NTOK * NTOK];
__device__ float g_pbm[NWIN * NH * NTOK * NTOK];
__device__ float g_lam;
// 12 chunks (q0,q1,k0,k1,v0,v1,q20,q21,k20,k21,p0,p1) x (hi image 16KB + lo image 16KB)
__device__ __nv_bfloat16 g_w[12 * 16384];

// ---------------------------------------------------------------------------
// Prep 1: polar-MLP bias table + lambda
// ---------------------------------------------------------------------------
__global__ void prep1_kernel(const float* __restrict__ Wp1, const float* __restrict__ bp1,
                             const float* __restrict__ Wp2, const float* __restrict__ bp2,
                             const float* __restrict__ lq1, const float* __restrict__ lk1,
                             const float* __restrict__ lq2, const float* __restrict__ lk2)
{
    int idx = blockIdx.x * blockDim.x + threadIdx.x;
    if (idx < NTOK * NTOK) {
        int i = idx >> 6, j = idx & 63;
        float dx = (float)(i & 7) - (float)(j & 7);
        float dy = -((float)(i >> 3) - (float)(j >> 3));
        float r  = sqrtf(dx * dx + dy * dy + 1e-9f);
        float th = atan2f(dx, dy);
        float p0 = r * 0.10101525445522107f;
        float p1 = (th + 3.14159265358979323846f) * 0.15915494309189535f;
        float o0 = __ldg(bp2 + 0), o1 = __ldg(bp2 + 1), o2 = __ldg(bp2 + 2), o3 = __ldg(bp2 + 3);
        for (int jj = 0; jj < 64; jj++) {
            float hv = fmaf(p0, __ldg(Wp1 + jj * 2), fmaf(p1, __ldg(Wp1 + jj * 2 + 1), __ldg(bp1 + jj)));
            float g  = 0.5f * hv * (1.0f + erff(hv * 0.7071067811865476f));
            o0 = fmaf(g, __ldg(Wp2 +       jj), o0);
            o1 = fmaf(g, __ldg(Wp2 +  64 + jj), o1);
            o2 = fmaf(g, __ldg(Wp2 + 128 + jj), o2);
            o3 = fmaf(g, __ldg(Wp2 + 192 + jj), o3);
        }
        g_pb[          idx] = o0;
        g_pb[ 4096 +   idx] = o1;
        g_pb[ 8192 +   idx] = o2;
        g_pb[12288 +   idx] = o3;
    }
    if (idx == 0) {
        float s1 = 0.f, s2 = 0.f;
        for (int k = 0; k < 16; k++) {
            s1 = fmaf(__ldg(lq1 + k), __ldg(lk1 + k), s1);
            s2 = fmaf(__ldg(lq2 + k), __ldg(lk2 + k), s2);
        }
        g_lam = expf(s1) - expf(s2) + 0.2f;
    }
}

__global__ void prep2_kernel(const float* __restrict__ mask)
{
    int idx = blockIdx.x * 256 + threadIdx.x;
    int rest = idx & 16383;
    int w    = idx >> 14;
    int nm   = idx & 4095;
    g_pbm[idx] = g_pb[rest] + __ldg(mask + w * 4096 + nm);
}

// Prep 3: bf16 hi/lo split of weights into swizzled ldmatrix images
__global__ void prepw_kernel(const float* __restrict__ Wqkv,
                             const float* __restrict__ Wqkv2,
                             const float* __restrict__ Wproj)
{
    int idx = blockIdx.x * 256 + threadIdx.x;   // 0..98303
    int c   = idx >> 13;                        // chunk 0..11 (8192 elems each)
    int rem = idx & 8191;
    int r = rem >> 7, k = rem & 127;            // r = col-in-chunk, k
    int cg = c * 64 + r;
    float v;
    if (cg < 384)      v = __ldg(Wqkv  + cg * 128 + k);
    else if (cg < 640) v = __ldg(Wqkv2 + (cg - 384) * 128 + k);
    else               v = __ldg(Wproj + (cg - 640) * 128 + k);
    __nv_bfloat16 h = __float2bfloat16(v);
    __nv_bfloat16 l = __float2bfloat16(v - __bfloat162float(h));
    int e = (c * 32768 + BSW(r, k * 2)) >> 1;   // hi image element
    g_w[e] = h;
    g_w[e + 8192] = l;                          // lo image +16KB
}

// ---------------------------------------------------------------------------
// 64xN cols MMA GEMM piece over one 64-col weight chunk (3-term hi/lo).
// ---------------------------------------------------------------------------
__device__ __forceinline__ void mma_chunk(u32 abase, u32 bbase, int mg, int wg, int lid,
                                          float d[2][4])
{
    #pragma unroll
    for (int nt = 0; nt < 2; nt++)
        #pragma unroll
        for (int i = 0; i < 4; i++) d[nt][i] = 0.f;
    const int ar = mg * 16 + (lid & 15);
    const int ak = (lid & 16);
    const int bc = wg * 16 + (lid & 7);
    const int bk = (lid & 8) << 1;
    #pragma unroll
    for (int ks = 0; ks < 8; ks++) {
        u32 ah[4], al[4];
        u32 aaddr = abase + BSW(ar, ks * 32 + ak);
        ldsm4(ah, aaddr);
        ldsm4(al, aaddr + 16384);
        #pragma unroll
        for (int nt = 0; nt < 2; nt++) {
            u32 bh[2], bl[2];
            u32 baddr = bbase + BSW(bc + nt * 8, ks * 32 + bk);
            ldsm2(bh, baddr);
            ldsm2(bl, baddr + 16384);
            mma16816(d[nt], ah, bh);
            mma16816(d[nt], ah, bl);
            mma16816(d[nt], al, bh);
        }
    }
}

// ---------------------------------------------------------------------------
// Main fused kernel, 512 threads. smem bytes (total 229376):
//   A [0,32768):       x bf16 hi/lo images       -> os fp32 SWZ tile after QKV
//   B [32768,65536):   W staging hi/lo (QKV)     -> att[64][68] fp32 -> os hi/lo images
//   C [65536,229376):  q img 65536/81920, k img 98304/114688, q2 img 131072/147456,
//                      k2 img 163840/180224, v fp32 tile 196608; q img reused for proj W
// ---------------------------------------------------------------------------
__global__ __launch_bounds__(NTHR) void wattn_kernel(
    const float* __restrict__ x,
    const float* __restrict__ bqkv, const float* __restrict__ bqkv2,
    const float* __restrict__ subln_w, const float* __restrict__ bproj,
    float* __restrict__ out)
{
    extern __shared__ float sm[];
    char* smc = (char*)sm;
    float* os  = sm;                       // region A (after QKV)
    float* att = sm + 8192;                // region B (during attention)
    float* vs  = (float*)(smc + 196608);   // fp32 SWZ tile

    const int b = blockIdx.x;
    const int t = threadIdx.x;
    const int w = t >> 5, lid = t & 31;
    const int mg = w & 3, wg = w >> 2;
    const u32 smb = sptr(sm);

    // ---- load x, split to bf16 hi/lo swizzled images (region A) ----
    const float4* xg = (const float4*)(x + (size_t)b * (NTOK * DIM));
    #pragma unroll
    for (int i = 0; i < 4; i++) {
        int idx = t + i * NTHR;                   // 2048 float4s
        int token = idx >> 5, kb = idx & 31;
        float4 v = __ldg(xg + idx);
        __nv_bfloat16 h0 = __float2bfloat16(v.x), h1 = __float2bfloat16(v.y);
        __nv_bfloat16 h2 = __float2bfloat16(v.z), h3 = __float2bfloat16(v.w);
        __nv_bfloat16 l0 = __float2bfloat16(v.x - __bfloat162float(h0));
        __nv_bfloat16 l1 = __float2bfloat16(v.y - __bfloat162float(h1));
        __nv_bfloat16 l2 = __float2bfloat16(v.z - __bfloat162float(h2));
        __nv_bfloat16 l3 = __float2bfloat16(v.w - __bfloat162float(h3));
        u64 hp = (u64)bfbits(h0) | ((u64)bfbits(h1) << 16) | ((u64)bfbits(h2) << 32) | ((u64)bfbits(h3) << 48);
        u64 lp = (u64)bfbits(l0) | ((u64)bfbits(l1) << 16) | ((u64)bfbits(l2) << 32) | ((u64)bfbits(l3) << 48);
        int sw = BSW(token, kb * 8);
        *(u64*)(smc + sw)         = hp;
        *(u64*)(smc + 16384 + sw) = lp;
    }
    __syncthreads();

    // ---- QKV: 10 chunks of 64 cols via mma.sync ----
    #pragma unroll 1
    for (int ch = 0; ch < 10; ch++) {
        const uint4* src = (const uint4*)((const char*)g_w + ch * 32768);
        uint4* dstp = (uint4*)(smc + 32768);
        #pragma unroll
        for (int i = 0; i < 4; i++) dstp[t + i * NTHR] = __ldg(src + t + i * NTHR);
        __syncthreads();

        float d[2][4];
        mma_chunk(smb, smb + 32768, mg, wg, lid, d);

        const int ten = ch >> 1;                  // 0:q 1:k 2:v 3:q2 4:k2
        const float mult = (ten == 0 || ten == 3) ? QSCALE : 1.0f;
        const float* bsrc = (ten < 3) ? (bqkv + ten * 128) : (bqkv2 + (ten - 3) * 128);
        const int r0 = mg * 16 + (lid >> 2);
        const int ibase = (ten == 0) ? 65536 : (ten == 1) ? 98304
                        : (ten == 3) ? 131072 : 163840;
        #pragma unroll
        for (int nt = 0; nt < 2; nt++) {
            int tc = (ch & 1) * 64 + wg * 16 + nt * 8 + 2 * (lid & 3);
            float b0 = __ldg(bsrc + tc), b1 = __ldg(bsrc + tc + 1);
            float v0 = (d[nt][0] + b0) * mult, v1 = (d[nt][1] + b1) * mult;
            float v2 = (d[nt][2] + b0) * mult, v3 = (d[nt][3] + b1) * mult;
            if (ten == 2) {
                int g = tc >> 2, sub = tc & 3;
                *(float2*)(vs + SWZ(r0,     g) * 4 + sub) = make_float2(v0, v1);
                *(float2*)(vs + SWZ(r0 + 8, g) * 4 + sub) = make_float2(v2, v3);
            } else {
                char* img = smc + ibase;
                int c2 = tc * 2;
                __nv_bfloat16 h0 = __float2bfloat16(v0), h1 = __float2bfloat16(v1);
                __nv_bfloat16 h2 = __float2bfloat16(v2), h3 = __float2bfloat16(v3);
                u32 hp01 = (u32)bfbits(h0) | ((u32)bfbits(h1) << 16);
                u32 hp23 = (u32)bfbits(h2) | ((u32)bfbits(h3) << 16);
                __nv_bfloat16 l0 = __float2bfloat16(v0 - __bfloat162float(h0));
                __nv_bfloat16 l1 = __float2bfloat16(v1 - __bfloat162float(h1));
                __nv_bfloat16 l2 = __float2bfloat16(v2 - __bfloat162float(h2));
                __nv_bfloat16 l3 = __float2bfloat16(v3 - __bfloat162float(h3));
                u32 lp01 = (u32)bfbits(l0) | ((u32)bfbits(l1) << 16);
                u32 lp23 = (u32)bfbits(l2) | ((u32)bfbits(l3) << 16);
                int s0 = BSW(r0, c2), s1 = BSW(r0 + 8, c2);
                *(u32*)(img + s0)         = hp01;
                *(u32*)(img + 16384 + s0) = lp01;
                *(u32*)(img + s1)         = hp23;
                *(u32*)(img + 16384 + s1) = lp23;
            }
        }
        __syncthreads();
    }

    // ---- differential attention ----
    const float lam = g_lam;
    const float* pbm = g_pbm + (size_t)(b % NWIN) * (NH * NTOK * NTOK);
    const int n = t >> 3, qd = t & 7;
    const ulonglong2* vu = (const ulonglong2*)vs;

    #pragma unroll 1
    for (int h = 0; h < NH; h++) {
        // -- logits via mma.sync: d1 = q.k^T, d2 = q2.k2^T (3-term hi/lo each) --
        {
            float d1[2][4], d2[2][4];
            #pragma unroll
            for (int nt = 0; nt < 2; nt++)
                #pragma unroll
                for (int i = 0; i < 4; i++) { d1[nt][i] = 0.f; d2[nt][i] = 0.f; }
            const int ar = mg * 16 + (lid & 15);
            const int abyte = h * 64 + (lid & 16);
            const int bc = wg * 16 + (lid & 7);
            const int bbyte = h * 64 + ((lid & 8) << 1);
            #pragma unroll
            for (int ks = 0; ks < 2; ks++) {
                u32 aoff = BSW(ar, abyte + ks * 32);
                u32 qh[4], ql[4], q2h[4], q2l[4];
                ldsm4(qh,  smb +  65536 + aoff);
                ldsm4(ql,  smb +  81920 + aoff);
                ldsm4(q2h, smb + 131072 + aoff);
                ldsm4(q2l, smb + 147456 + aoff);
                #pragma unroll
                for (int nt = 0; nt < 2; nt++) {
                    u32 boff = BSW(bc + nt * 8, bbyte + ks * 32);
                    u32 kh[2], kl[2], k2h[2], k2l[2];
                    ldsm2(kh,  smb +  98304 + boff);
                    ldsm2(kl,  smb + 114688 + boff);
                    ldsm2(k2h, smb + 163840 + boff);
                    ldsm2(k2l, smb + 180224 + boff);
                    mma16816(d1[nt], qh, kh);
                    mma16816(d1[nt], qh, kl);
                    mma16816(d1[nt], ql, kh);
                    mma16816(d2[nt], q2h, k2h);
                    mma16816(d2[nt], q2h, k2l);
                    mma16816(d2[nt], q2l, k2h);
                }
            }
            const int r0 = mg * 16 + (lid >> 2);
            #pragma unroll
            for (int nt = 0; nt < 2; nt++) {
                int col = wg * 16 + nt * 8 + 2 * (lid & 3);
                float2 p0 = __ldg((const float2*)(pbm + h * 4096 + r0 * 64 + col));
                float2 p1 = __ldg((const float2*)(pbm + h * 4096 + (r0 + 8) * 64 + col));
                *(float2*)(att + r0 * 68 + col) =
                    make_float2(fmaf(-lam, d2[nt][0], d1[nt][0]) + p0.x,
                                fmaf(-lam, d2[nt][1], d1[nt][1]) + p0.y);
                *(float2*)(att + (r0 + 8) * 68 + col) =
                    make_float2(fmaf(-lam, d2[nt][2], d1[nt][2]) + p1.x,
                                fmaf(-lam, d2[nt][3], d1[nt][3]) + p1.y);
            }
        }
        __syncthreads();

        // -- softmax (8 lanes per row) --
        float lg[8];
        #pragma unroll
        for (int j = 0; j < 8; j++) lg[j] = att[n * 68 + qd + 8 * j];
        float M = lg[0];
        #pragma unroll
        for (int j = 1; j < 8; j++) M = fmaxf(M, lg[j]);
        M = fmaxf(M, __shfl_xor_sync(0xffffffffu, M, 1));
        M = fmaxf(M, __shfl_xor_sync(0xffffffffu, M, 2));
        M = fmaxf(M, __shfl_xor_sync(0xffffffffu, M, 4));
        float S = 0.f;
        #pragma unroll
        for (int j = 0; j < 8; j++) { lg[j] = __expf(lg[j] - M); S += lg[j]; }
        S += __shfl_xor_sync(0xffffffffu, S, 1);
        S += __shfl_xor_sync(0xffffffffu, S, 2);
        S += __shfl_xor_sync(0xffffffffu, S, 4);
        float inv = 1.0f / S;
        #pragma unroll
        for (int j = 0; j < 8; j++) att[n * 68 + qd + 8 * j] = lg[j] * inv;
        __syncthreads();

        // -- o = P @ V (SIMT; v-loads are 8-address broadcasts) --
        const int ho4 = h * 8;
        u64 o2[2] = {0ull, 0ull};
        const int gv = ho4 + qd;
        #pragma unroll 4
        for (int jm = 0; jm < 16; jm++) {
            float4 p4 = *(const float4*)(att + n * 68 + jm * 4);
            #pragma unroll
            for (int mm = 0; mm < 4; mm++) {
                int m = jm * 4 + mm;
                float pv = (mm == 0) ? p4.x : (mm == 1) ? p4.y : (mm == 2) ? p4.z : p4.w;
                u64 pp = pack2(pv, pv);
                ulonglong2 v0 = vu[m * 32 + (gv ^ (m & 31))];
                ffma2(o2[0], pp, v0.x); ffma2(o2[1], pp, v0.y);
            }
        }
        u64 sq = 0ull;
        ffma2(sq, o2[0], o2[0]);
        ffma2(sq, o2[1], o2[1]);
        float ss = lo2(sq) + hi2(sq);
        ss += __shfl_xor_sync(0xffffffffu, ss, 1);
        ss += __shfl_xor_sync(0xffffffffu, ss, 2);
        ss += __shfl_xor_sync(0xffffffffu, ss, 4);
        float rs = rsqrtf(ss * (1.0f / 32.0f) + 1e-9f) * OUTS;
        float4 sW = __ldg((const float4*)subln_w + qd);
        float4 r0;
        r0.x = lo2(o2[0]) * rs * sW.x;  r0.y = hi2(o2[0]) * rs * sW.y;
        r0.z = lo2(o2[1]) * rs * sW.z;  r0.w = hi2(o2[1]) * rs * sW.w;
        ((float4*)os)[SWZ(n, gv)] = r0;
        __syncthreads();
    }

    // ---- convert os -> bf16 hi/lo images in region B ----
    #pragma unroll
    for (int i = 0; i < 4; i++) {
        int idx = t + i * NTHR;
        int token = idx >> 5, g4 = idx & 31;
        float4 v = ((const float4*)os)[SWZ(token, g4)];
        __nv_bfloat16 h0 = __float2bfloat16(v.x), h1 = __float2bfloat16(v.y);
        __nv_bfloat16 h2 = __float2bfloat16(v.z), h3 = __float2bfloat16(v.w);
        __nv_bfloat16 l0 = __float2bfloat16(v.x - __bfloat162float(h0));
        __nv_bfloat16 l1 = __float2bfloat16(v.y - __bfloat162float(h1));
        __nv_bfloat16 l2 = __float2bfloat16(v.z - __bfloat162float(h2));
        __nv_bfloat16 l3 = __float2bfloat16(v.w - __bfloat162float(h3));
        u64 hp = (u64)bfbits(h0) | ((u64)bfbits(h1) << 16) | ((u64)bfbits(h2) << 32) | ((u64)bfbits(h3) << 48);
        u64 lp = (u64)bfbits(l0) | ((u64)bfbits(l1) << 16) | ((u64)bfbits(l2) << 32) | ((u64)bfbits(l3) << 48);
        int sw = BSW(token, g4 * 8);
        *(u64*)(smc + 32768 + sw) = hp;
        *(u64*)(smc + 49152 + sw) = lp;
    }

    // ---- proj: 2 chunks of 64 cols; W staged in (dead) q-image region ----
    float* og = out + (size_t)b * (NTOK * DIM);
    #pragma unroll 1
    for (int pc = 0; pc < 2; pc++) {
        const uint4* src = (const uint4*)((const char*)g_w + (10 + pc) * 32768);
        uint4* dstp = (uint4*)(smc + 65536);
        #pragma unroll
        for (int i = 0; i < 4; i++) dstp[t + i * NTHR] = __ldg(src + t + i * NTHR);
        __syncthreads();

        float d[2][4];
        mma_chunk(smb + 32768, smb + 65536, mg, wg, lid, d);

        const int r0 = mg * 16 + (lid >> 2);
        #pragma unroll
        for (int nt = 0; nt < 2; nt++) {
            int cg = pc * 64 + wg * 16 + nt * 8 + 2 * (lid & 3);
            float b0 = __ldg(bproj + cg), b1 = __ldg(bproj + cg + 1);
            *(float2*)(og + r0 * 128 + cg)       = make_float2(d[nt][0] + b0, d[nt][1] + b1);
            *(float2*)(og + (r0 + 8) * 128 + cg) = make_float2(d[nt][2] + b0, d[nt][3] + b1);
        }
        __syncthreads();
    }
}

// ---------------------------------------------------------------------------
extern "C" void kernel_launch(void* const* d_in, const int* in_sizes, int n_in,
                              void* d_out, int out_size)
{
    const float* x      = (const float*)d_in[0];
    const float* mask   = (const float*)d_in[1];
    const float* Wqkv   = (const float*)d_in[2];
    const float* bqkv   = (const float*)d_in[3];
    const float* Wqkv2  = (const float*)d_in[4];
    const float* bqkv2  = (const float*)d_in[5];
    const float* Wp1    = (const float*)d_in[6];
    const float* bp1    = (const float*)d_in[7];
    const float* Wp2    = (const float*)d_in[8];
    const float* bp2    = (const float*)d_in[9];
    const float* lq1    = (const float*)d_in[10];
    const float* lk1    = (const float*)d_in[11];
    const float* lq2    = (const float*)d_in[12];
    const float* lk2    = (const float*)d_in[13];
    const float* subln  = (const float*)d_in[14];
    const float* Wproj  = (const float*)d_in[15];
    const float* bproj  = (const float*)d_in[16];
    float* out = (float*)d_out;

    const int SMEM = 229376;
    cudaFuncSetAttribute(wattn_kernel, cudaFuncAttributeMaxDynamicSharedMemorySize, SMEM);

    prep1_kernel<<<16, 256>>>(Wp1, bp1, Wp2, bp2, lq1, lk1, lq2, lk2);
    prep2_kernel<<<(NWIN * NH * NTOK * NTOK) / 256, 256>>>(mask);
    prepw_kernel<<<384, 256>>>(Wqkv, Wqkv2, Wproj);
    wattn_kernel<<<B_TOT, NTHR, SMEM>>>(x, bqkv, bqkv2, subln, bproj, out);
}

// round 10
// speedup vs baseline: 3.0886x; 1.2061x over previous
#include <cuda_runtime.h>
#include <cuda_bf16.h>
#include <math.h>

typedef unsigned long long u64;
typedef unsigned int u32;

#define B_TOT 3072
#define NTOK  64
#define DIM   128
#define NH    4
#define NWIN  192
#define NTHR  512
#define QSCALE 0.1767766952966369f   // 32^-0.5
#define OUTS   0.8f                  // 1 - lambda_init

// fp32 tile swizzle: f4-unit index in [64 rows][32 f4]
__device__ __forceinline__ int SWZ(int row, int g) { return row * 32 + (g ^ (row & 31)); }
// bf16 image swizzle: byte offset in [64 rows][256B rows]
__device__ __forceinline__ int BSW(int r, int byte) {
    return r * 256 + ((((byte >> 4) ^ r) & 15) << 4) + (byte & 15);
}
// bf16 image swizzle for 128B rows (P image)
__device__ __forceinline__ int BSW128(int r, int byte) {
    return r * 128 + ((((byte >> 4) ^ r) & 7) << 4) + (byte & 15);
}

// ---------------- mma.sync helpers (portable sm_80+ ISA) ----------------
__device__ __forceinline__ u32 sptr(const void* p) { return (u32)__cvta_generic_to_shared(p); }
__device__ __forceinline__ void ldsm4(u32 r[4], u32 addr) {
    asm volatile("ldmatrix.sync.aligned.m8n8.x4.shared.b16 {%0,%1,%2,%3}, [%4];"
                 : "=r"(r[0]), "=r"(r[1]), "=r"(r[2]), "=r"(r[3]) : "r"(addr));
}
__device__ __forceinline__ void ldsm2(u32 r[2], u32 addr) {
    asm volatile("ldmatrix.sync.aligned.m8n8.x2.shared.b16 {%0,%1}, [%2];"
                 : "=r"(r[0]), "=r"(r[1]) : "r"(addr));
}
__device__ __forceinline__ void ldsm2t(u32 r[2], u32 addr) {
    asm volatile("ldmatrix.sync.aligned.m8n8.x2.trans.shared.b16 {%0,%1}, [%2];"
                 : "=r"(r[0]), "=r"(r[1]) : "r"(addr));
}
__device__ __forceinline__ void mma16816(float d[4], const u32 a[4], const u32 b[2]) {
    asm volatile("mma.sync.aligned.m16n8k16.row.col.f32.bf16.bf16.f32 "
                 "{%0,%1,%2,%3}, {%4,%5,%6,%7}, {%8,%9}, {%0,%1,%2,%3};"
                 : "+f"(d[0]), "+f"(d[1]), "+f"(d[2]), "+f"(d[3])
                 : "r"(a[0]), "r"(a[1]), "r"(a[2]), "r"(a[3]), "r"(b[0]), "r"(b[1]));
}
__device__ __forceinline__ unsigned short bfbits(__nv_bfloat16 h) {
    return *reinterpret_cast<unsigned short*>(&h);
}

__device__ float g_pb[NH * NTOK * NTOK];
__device__ float g_pbm[NWIN * NH * NTOK * NTOK];
__device__ float g_lam;
// 12 chunks (q0,q1,k0,k1,v0,v1,q20,q21,k20,k21,p0,p1) x (hi 16KB + lo 16KB)
__device__ __nv_bfloat16 g_w[12 * 16384];

// ---------------------------------------------------------------------------
__global__ void prep1_kernel(const float* __restrict__ Wp1, const float* __restrict__ bp1,
                             const float* __restrict__ Wp2, const float* __restrict__ bp2,
                             const float* __restrict__ lq1, const float* __restrict__ lk1,
                             const float* __restrict__ lq2, const float* __restrict__ lk2)
{
    int idx = blockIdx.x * blockDim.x + threadIdx.x;
    if (idx < NTOK * NTOK) {
        int i = idx >> 6, j = idx & 63;
        float dx = (float)(i & 7) - (float)(j & 7);
        float dy = -((float)(i >> 3) - (float)(j >> 3));
        float r  = sqrtf(dx * dx + dy * dy + 1e-9f);
        float th = atan2f(dx, dy);
        float p0 = r * 0.10101525445522107f;
        float p1 = (th + 3.14159265358979323846f) * 0.15915494309189535f;
        float o0 = __ldg(bp2 + 0), o1 = __ldg(bp2 + 1), o2 = __ldg(bp2 + 2), o3 = __ldg(bp2 + 3);
        for (int jj = 0; jj < 64; jj++) {
            float hv = fmaf(p0, __ldg(Wp1 + jj * 2), fmaf(p1, __ldg(Wp1 + jj * 2 + 1), __ldg(bp1 + jj)));
            float g  = 0.5f * hv * (1.0f + erff(hv * 0.7071067811865476f));
            o0 = fmaf(g, __ldg(Wp2 +       jj), o0);
            o1 = fmaf(g, __ldg(Wp2 +  64 + jj), o1);
            o2 = fmaf(g, __ldg(Wp2 + 128 + jj), o2);
            o3 = fmaf(g, __ldg(Wp2 + 192 + jj), o3);
        }
        g_pb[          idx] = o0;
        g_pb[ 4096 +   idx] = o1;
        g_pb[ 8192 +   idx] = o2;
        g_pb[12288 +   idx] = o3;
    }
    if (idx == 0) {
        float s1 = 0.f, s2 = 0.f;
        for (int k = 0; k < 16; k++) {
            s1 = fmaf(__ldg(lq1 + k), __ldg(lk1 + k), s1);
            s2 = fmaf(__ldg(lq2 + k), __ldg(lk2 + k), s2);
        }
        g_lam = expf(s1) - expf(s2) + 0.2f;
    }
}

__global__ void prep2_kernel(const float* __restrict__ mask)
{
    int idx = blockIdx.x * 256 + threadIdx.x;
    int rest = idx & 16383;
    int w    = idx >> 14;
    int nm   = idx & 4095;
    g_pbm[idx] = g_pb[rest] + __ldg(mask + w * 4096 + nm);
}

// Prep 3: bf16 hi/lo split of weights into swizzled ldmatrix images.
// Folds QSCALE into q/q2 weights and subln*(1-lambda_init) into proj weights.
__global__ void prepw_kernel(const float* __restrict__ Wqkv,
                             const float* __restrict__ Wqkv2,
                             const float* __restrict__ Wproj,
                             const float* __restrict__ subln)
{
    int idx = blockIdx.x * 256 + threadIdx.x;   // 0..98303
    int c   = idx >> 13;                        // chunk 0..11
    int rem = idx & 8191;
    int r = rem >> 7, k = rem & 127;
    int cg = c * 64 + r;
    float v, scale = 1.0f;
    if (cg < 384)      { v = __ldg(Wqkv  + cg * 128 + k);         if (cg < 128) scale = QSCALE; }
    else if (cg < 640) { v = __ldg(Wqkv2 + (cg - 384) * 128 + k); if (cg < 512) scale = QSCALE; }
    else               { v = __ldg(Wproj + (cg - 640) * 128 + k); scale = __ldg(subln + (k & 31)) * OUTS; }
    v *= scale;
    __nv_bfloat16 h = __float2bfloat16(v);
    __nv_bfloat16 l = __float2bfloat16(v - __bfloat162float(h));
    int e = (c * 32768 + BSW(r, k * 2)) >> 1;
    g_w[e] = h;
    g_w[e + 8192] = l;
}

// ---------------------------------------------------------------------------
// 64x64 MMA GEMM piece over one 64-col weight chunk (3-term hi/lo).
// ---------------------------------------------------------------------------
__device__ __forceinline__ void mma_chunk(u32 abase, u32 bbase, int mg, int wg, int lid,
                                          float d[2][4])
{
    #pragma unroll
    for (int nt = 0; nt < 2; nt++)
        #pragma unroll
        for (int i = 0; i < 4; i++) d[nt][i] = 0.f;
    const int ar = mg * 16 + (lid & 15);
    const int ak = (lid & 16);
    const int bc = wg * 16 + (lid & 7);
    const int bk = (lid & 8) << 1;
    #pragma unroll
    for (int ks = 0; ks < 8; ks++) {
        u32 ah[4], al[4];
        u32 aaddr = abase + BSW(ar, ks * 32 + ak);
        ldsm4(ah, aaddr);
        ldsm4(al, aaddr + 16384);
        #pragma unroll
        for (int nt = 0; nt < 2; nt++) {
            u32 bh[2], bl[2];
            u32 baddr = bbase + BSW(bc + nt * 8, ks * 32 + bk);
            ldsm2(bh, baddr);
            ldsm2(bl, baddr + 16384);
            mma16816(d[nt], ah, bh);
            mma16816(d[nt], ah, bl);
            mma16816(d[nt], al, bh);
        }
    }
}

// ---------------------------------------------------------------------------
// Main fused kernel, 512 threads. smem bytes (total 229376):
//   A [0,32768):       x bf16 hi/lo images  -> os fp32 SWZ tile after QKV
//   B [32768,65536):   W staging (QKV)      -> att fp32 (stride 68) / P hi@32768, lo@40960
//                                           -> os hi/lo images for proj
//   C [65536,229376):  images: q 65536/81920, k 98304/114688, q2 131072/147456,
//                      k2 163840/180224, v 196608/212992; q region reused for proj W
// ---------------------------------------------------------------------------
__global__ __launch_bounds__(NTHR) void wattn_kernel(
    const float* __restrict__ x,
    const float* __restrict__ bqkv, const float* __restrict__ bqkv2,
    const float* __restrict__ bproj,
    float* __restrict__ out)
{
    extern __shared__ float sm[];
    char* smc = (char*)sm;
    float* os  = sm;                       // region A (after QKV)
    float* att = sm + 8192;                // region B

    const int b = blockIdx.x;
    const int t = threadIdx.x;
    const int w = t >> 5, lid = t & 31;
    const int mg = w & 3, wg = w >> 2;
    const u32 smb = sptr(sm);

    // ---- load x, split to bf16 hi/lo swizzled images (region A) ----
    const float4* xg = (const float4*)(x + (size_t)b * (NTOK * DIM));
    #pragma unroll
    for (int i = 0; i < 4; i++) {
        int idx = t + i * NTHR;
        int token = idx >> 5, kb = idx & 31;
        float4 v = __ldg(xg + idx);
        __nv_bfloat16 h0 = __float2bfloat16(v.x), h1 = __float2bfloat16(v.y);
        __nv_bfloat16 h2 = __float2bfloat16(v.z), h3 = __float2bfloat16(v.w);
        __nv_bfloat16 l0 = __float2bfloat16(v.x - __bfloat162float(h0));
        __nv_bfloat16 l1 = __float2bfloat16(v.y - __bfloat162float(h1));
        __nv_bfloat16 l2 = __float2bfloat16(v.z - __bfloat162float(h2));
        __nv_bfloat16 l3 = __float2bfloat16(v.w - __bfloat162float(h3));
        u64 hp = (u64)bfbits(h0) | ((u64)bfbits(h1) << 16) | ((u64)bfbits(h2) << 32) | ((u64)bfbits(h3) << 48);
        u64 lp = (u64)bfbits(l0) | ((u64)bfbits(l1) << 16) | ((u64)bfbits(l2) << 32) | ((u64)bfbits(l3) << 48);
        int sw = BSW(token, kb * 8);
        *(u64*)(smc + sw)         = hp;
        *(u64*)(smc + 16384 + sw) = lp;
    }
    __syncthreads();

    // ---- QKV: 10 chunks of 64 cols via mma.sync; all outputs -> bf16 images ----
    #pragma unroll 1
    for (int ch = 0; ch < 10; ch++) {
        const uint4* src = (const uint4*)((const char*)g_w + ch * 32768);
        uint4* dstp = (uint4*)(smc + 32768);
        #pragma unroll
        for (int i = 0; i < 4; i++) dstp[t + i * NTHR] = __ldg(src + t + i * NTHR);
        __syncthreads();

        float d[2][4];
        mma_chunk(smb, smb + 32768, mg, wg, lid, d);

        const int ten = ch >> 1;                  // 0:q 1:k 2:v 3:q2 4:k2
        const float bmult = (ten == 0 || ten == 3) ? QSCALE : 1.0f;
        const float* bsrc = (ten < 3) ? (bqkv + ten * 128) : (bqkv2 + (ten - 3) * 128);
        const int r0 = mg * 16 + (lid >> 2);
        const int ibase = (ten == 0) ? 65536 : (ten == 1) ? 98304
                        : (ten == 2) ? 196608 : (ten == 3) ? 131072 : 163840;
        char* img = smc + ibase;
        #pragma unroll
        for (int nt = 0; nt < 2; nt++) {
            int tc = (ch & 1) * 64 + wg * 16 + nt * 8 + 2 * (lid & 3);
            float b0 = __ldg(bsrc + tc) * bmult, b1 = __ldg(bsrc + tc + 1) * bmult;
            float v0 = d[nt][0] + b0, v1 = d[nt][1] + b1;
            float v2 = d[nt][2] + b0, v3 = d[nt][3] + b1;
            int c2 = tc * 2;
            __nv_bfloat16 h0 = __float2bfloat16(v0), h1 = __float2bfloat16(v1);
            __nv_bfloat16 h2 = __float2bfloat16(v2), h3 = __float2bfloat16(v3);
            u32 hp01 = (u32)bfbits(h0) | ((u32)bfbits(h1) << 16);
            u32 hp23 = (u32)bfbits(h2) | ((u32)bfbits(h3) << 16);
            __nv_bfloat16 l0 = __float2bfloat16(v0 - __bfloat162float(h0));
            __nv_bfloat16 l1 = __float2bfloat16(v1 - __bfloat162float(h1));
            __nv_bfloat16 l2 = __float2bfloat16(v2 - __bfloat162float(h2));
            __nv_bfloat16 l3 = __float2bfloat16(v3 - __bfloat162float(h3));
            u32 lp01 = (u32)bfbits(l0) | ((u32)bfbits(l1) << 16);
            u32 lp23 = (u32)bfbits(l2) | ((u32)bfbits(l3) << 16);
            int s0 = BSW(r0, c2), s1 = BSW(r0 + 8, c2);
            *(u32*)(img + s0)         = hp01;
            *(u32*)(img + 16384 + s0) = lp01;
            *(u32*)(img + s1)         = hp23;
            *(u32*)(img + 16384 + s1) = lp23;
        }
        __syncthreads();
    }

    // ---- differential attention: fully tensor-core ----
    const float lam = g_lam;
    const float* pbm = g_pbm + (size_t)(b % NWIN) * (NH * NTOK * NTOK);
    const int n = t >> 3, qd = t & 7;

    #pragma unroll 1
    for (int h = 0; h < NH; h++) {
        // -- logits via mma.sync: d1 = q.k^T, d2 = q2.k2^T --
        {
            float d1[2][4], d2[2][4];
            #pragma unroll
            for (int nt = 0; nt < 2; nt++)
                #pragma unroll
                for (int i = 0; i < 4; i++) { d1[nt][i] = 0.f; d2[nt][i] = 0.f; }
            const int ar = mg * 16 + (lid & 15);
            const int abyte = h * 64 + (lid & 16);
            const int bc = wg * 16 + (lid & 7);
            const int bbyte = h * 64 + ((lid & 8) << 1);
            #pragma unroll
            for (int ks = 0; ks < 2; ks++) {
                u32 aoff = BSW(ar, abyte + ks * 32);
                u32 qh[4], ql[4], q2h[4], q2l[4];
                ldsm4(qh,  smb +  65536 + aoff);
                ldsm4(ql,  smb +  81920 + aoff);
                ldsm4(q2h, smb + 131072 + aoff);
                ldsm4(q2l, smb + 147456 + aoff);
                #pragma unroll
                for (int nt = 0; nt < 2; nt++) {
                    u32 boff = BSW(bc + nt * 8, bbyte + ks * 32);
                    u32 kh[2], kl[2], k2h[2], k2l[2];
                    ldsm2(kh,  smb +  98304 + boff);
                    ldsm2(kl,  smb + 114688 + boff);
                    ldsm2(k2h, smb + 163840 + boff);
                    ldsm2(k2l, smb + 180224 + boff);
                    mma16816(d1[nt], qh, kh);
                    mma16816(d1[nt], qh, kl);
                    mma16816(d1[nt], ql, kh);
                    mma16816(d2[nt], q2h, k2h);
                    mma16816(d2[nt], q2h, k2l);
                    mma16816(d2[nt], q2l, k2h);
                }
            }
            const int r0 = mg * 16 + (lid >> 2);
            #pragma unroll
            for (int nt = 0; nt < 2; nt++) {
                int col = wg * 16 + nt * 8 + 2 * (lid & 3);
                float2 p0 = __ldg((const float2*)(pbm + h * 4096 + r0 * 64 + col));
                float2 p1 = __ldg((const float2*)(pbm + h * 4096 + (r0 + 8) * 64 + col));
                *(float2*)(att + r0 * 68 + col) =
                    make_float2(fmaf(-lam, d2[nt][0], d1[nt][0]) + p0.x,
                                fmaf(-lam, d2[nt][1], d1[nt][1]) + p0.y);
                *(float2*)(att + (r0 + 8) * 68 + col) =
                    make_float2(fmaf(-lam, d2[nt][2], d1[nt][2]) + p1.x,
                                fmaf(-lam, d2[nt][3], d1[nt][3]) + p1.y);
            }
        }
        __syncthreads();

        // -- softmax: lane owns 8 contiguous cols [qd*8, qd*8+8) of row n --
        float p[8];
        {
            float4 L0 = *(const float4*)(att + n * 68 + qd * 8);
            float4 L1 = *(const float4*)(att + n * 68 + qd * 8 + 4);
            p[0] = L0.x; p[1] = L0.y; p[2] = L0.z; p[3] = L0.w;
            p[4] = L1.x; p[5] = L1.y; p[6] = L1.z; p[7] = L1.w;
        }
        __syncthreads();   // all att reads done before P overwrites region B
        {
            float M = p[0];
            #pragma unroll
            for (int j = 1; j < 8; j++) M = fmaxf(M, p[j]);
            M = fmaxf(M, __shfl_xor_sync(0xffffffffu, M, 1));
            M = fmaxf(M, __shfl_xor_sync(0xffffffffu, M, 2));
            M = fmaxf(M, __shfl_xor_sync(0xffffffffu, M, 4));
            float S = 0.f;
            #pragma unroll
            for (int j = 0; j < 8; j++) { p[j] = __expf(p[j] - M); S += p[j]; }
            S += __shfl_xor_sync(0xffffffffu, S, 1);
            S += __shfl_xor_sync(0xffffffffu, S, 2);
            S += __shfl_xor_sync(0xffffffffu, S, 4);
            float inv = 1.0f / S;
            u32 hp[4], lp[4];
            #pragma unroll
            for (int j = 0; j < 4; j++) {
                float v0 = p[2 * j] * inv, v1 = p[2 * j + 1] * inv;
                __nv_bfloat16 h0 = __float2bfloat16(v0), h1 = __float2bfloat16(v1);
                hp[j] = (u32)bfbits(h0) | ((u32)bfbits(h1) << 16);
                __nv_bfloat16 l0 = __float2bfloat16(v0 - __bfloat162float(h0));
                __nv_bfloat16 l1 = __float2bfloat16(v1 - __bfloat162float(h1));
                lp[j] = (u32)bfbits(l0) | ((u32)bfbits(l1) << 16);
            }
            int sw = BSW128(n, qd * 16);
            *(uint4*)(smc + 32768 + sw) = make_uint4(hp[0], hp[1], hp[2], hp[3]);
            *(uint4*)(smc + 40960 + sw) = make_uint4(lp[0], lp[1], lp[2], lp[3]);
        }
        __syncthreads();

        // -- o = P @ V via mma.sync (V fragment via ldmatrix.trans) --
        {
            float d[4] = {0.f, 0.f, 0.f, 0.f};
            const int ar = mg * 16 + (lid & 15);
            const int ak = (lid & 16);
            #pragma unroll
            for (int ks = 0; ks < 4; ks++) {
                u32 ph[4], pl[4];
                u32 paddr = smb + 32768 + BSW128(ar, ks * 32 + ak);
                ldsm4(ph, paddr);
                ldsm4(pl, paddr + 8192);
                u32 vh[2], vl[2];
                u32 vaddr = smb + 196608 + BSW(ks * 16 + (lid & 15), h * 64 + wg * 16);
                ldsm2t(vh, vaddr);
                ldsm2t(vl, vaddr + 16384);
                mma16816(d, ph, vh);
                mma16816(d, ph, vl);
                mma16816(d, pl, vh);
            }
            const int r0 = mg * 16 + (lid >> 2);
            int c = h * 32 + wg * 8 + 2 * (lid & 3);
            int g = c >> 2, sub = c & 3;
            *(float2*)(os + SWZ(r0, g) * 4 + sub)     = make_float2(d[0], d[1]);
            *(float2*)(os + SWZ(r0 + 8, g) * 4 + sub) = make_float2(d[2], d[3]);
        }
        __syncthreads();   // P/att dead before next head's logit stores
    }

    // ---- RMSNorm over head_dim, in place (subln & OUTS folded into Wproj) ----
    {
        #pragma unroll
        for (int h = 0; h < NH; h++) {
            int g = h * 8 + qd;
            float4 v4 = ((const float4*)os)[SWZ(n, g)];
            float s = v4.x * v4.x + v4.y * v4.y + v4.z * v4.z + v4.w * v4.w;
            s += __shfl_xor_sync(0xffffffffu, s, 1);
            s += __shfl_xor_sync(0xffffffffu, s, 2);
            s += __shfl_xor_sync(0xffffffffu, s, 4);
            float rs = rsqrtf(s * (1.0f / 32.0f) + 1e-9f);
            v4.x *= rs; v4.y *= rs; v4.z *= rs; v4.w *= rs;
            ((float4*)os)[SWZ(n, g)] = v4;
        }
    }
    __syncthreads();

    // ---- convert os -> bf16 hi/lo images in region B ----
    #pragma unroll
    for (int i = 0; i < 4; i++) {
        int idx = t + i * NTHR;
        int token = idx >> 5, g4 = idx & 31;
        float4 v = ((const float4*)os)[SWZ(token, g4)];
        __nv_bfloat16 h0 = __float2bfloat16(v.x), h1 = __float2bfloat16(v.y);
        __nv_bfloat16 h2 = __float2bfloat16(v.z), h3 = __float2bfloat16(v.w);
        __nv_bfloat16 l0 = __float2bfloat16(v.x - __bfloat162float(h0));
        __nv_bfloat16 l1 = __float2bfloat16(v.y - __bfloat162float(h1));
        __nv_bfloat16 l2 = __float2bfloat16(v.z - __bfloat162float(h2));
        __nv_bfloat16 l3 = __float2bfloat16(v.w - __bfloat162float(h3));
        u64 hp = (u64)bfbits(h0) | ((u64)bfbits(h1) << 16) | ((u64)bfbits(h2) << 32) | ((u64)bfbits(h3) << 48);
        u64 lp = (u64)bfbits(l0) | ((u64)bfbits(l1) << 16) | ((u64)bfbits(l2) << 32) | ((u64)bfbits(l3) << 48);
        int sw = BSW(token, g4 * 8);
        *(u64*)(smc + 32768 + sw) = hp;
        *(u64*)(smc + 49152 + sw) = lp;
    }

    // ---- proj: 2 chunks of 64 cols; W staged in (dead) q-image region ----
    float* og = out + (size_t)b * (NTOK * DIM);
    #pragma unroll 1
    for (int pc = 0; pc < 2; pc++) {
        const uint4* src = (const uint4*)((const char*)g_w + (10 + pc) * 32768);
        uint4* dstp = (uint4*)(smc + 65536);
        #pragma unroll
        for (int i = 0; i < 4; i++) dstp[t + i * NTHR] = __ldg(src + t + i * NTHR);
        __syncthreads();

        float d[2][4];
        mma_chunk(smb + 32768, smb + 65536, mg, wg, lid, d);

        const int r0 = mg * 16 + (lid >> 2);
        #pragma unroll
        for (int nt = 0; nt < 2; nt++) {
            int cg = pc * 64 + wg * 16 + nt * 8 + 2 * (lid & 3);
            float b0 = __ldg(bproj + cg), b1 = __ldg(bproj + cg + 1);
            *(float2*)(og + r0 * 128 + cg)       = make_float2(d[nt][0] + b0, d[nt][1] + b1);
            *(float2*)(og + (r0 + 8) * 128 + cg) = make_float2(d[nt][2] + b0, d[nt][3] + b1);
        }
        __syncthreads();
    }
}

// ---------------------------------------------------------------------------
extern "C" void kernel_launch(void* const* d_in, const int* in_sizes, int n_in,
                              void* d_out, int out_size)
{
    const float* x      = (const float*)d_in[0];
    const float* mask   = (const float*)d_in[1];
    const float* Wqkv   = (const float*)d_in[2];
    const float* bqkv   = (const float*)d_in[3];
    const float* Wqkv2  = (const float*)d_in[4];
    const float* bqkv2  = (const float*)d_in[5];
    const float* Wp1    = (const float*)d_in[6];
    const float* bp1    = (const float*)d_in[7];
    const float* Wp2    = (const float*)d_in[8];
    const float* bp2    = (const float*)d_in[9];
    const float* lq1    = (const float*)d_in[10];
    const float* lk1    = (const float*)d_in[11];
    const float* lq2    = (const float*)d_in[12];
    const float* lk2    = (const float*)d_in[13];
    const float* subln  = (const float*)d_in[14];
    const float* Wproj  = (const float*)d_in[15];
    const float* bproj  = (const float*)d_in[16];
    float* out = (float*)d_out;

    const int SMEM = 229376;
    cudaFuncSetAttribute(wattn_kernel, cudaFuncAttributeMaxDynamicSharedMemorySize, SMEM);

    prep1_kernel<<<16, 256>>>(Wp1, bp1, Wp2, bp2, lq1, lk1, lq2, lk2);
    prep2_kernel<<<(NWIN * NH * NTOK * NTOK) / 256, 256>>>(mask);
    prepw_kernel<<<384, 256>>>(Wqkv, Wqkv2, Wproj, subln);
    wattn_kernel<<<B_TOT, NTHR, SMEM>>>(x, bqkv, bqkv2, bproj, out);
}

// round 11
// speedup vs baseline: 3.4055x; 1.1026x over previous
#include <cuda_runtime.h>
#include <cuda_bf16.h>
#include <math.h>

typedef unsigned long long u64;
typedef unsigned int u32;

#define B_TOT 3072
#define NTOK  64
#define DIM   128
#define NH    4
#define NWIN  192
#define NTHR  512
#define QSCALE 0.1767766952966369f   // 32^-0.5
#define OUTS   0.8f                  // 1 - lambda_init

// fp32 tile swizzle: f4-unit index in [64 rows][32 f4]
__device__ __forceinline__ int SWZ(int row, int g) { return row * 32 + (g ^ (row & 31)); }
// bf16 image swizzle: byte offset in [64 rows][256B rows]
__device__ __forceinline__ int BSW(int r, int byte) {
    return r * 256 + ((((byte >> 4) ^ r) & 15) << 4) + (byte & 15);
}
// bf16 image swizzle for 128B rows (P image)
__device__ __forceinline__ int BSW128(int r, int byte) {
    return r * 128 + ((((byte >> 4) ^ r) & 7) << 4) + (byte & 15);
}

// ---------------- mma.sync helpers (portable sm_80+ ISA) ----------------
__device__ __forceinline__ u32 sptr(const void* p) { return (u32)__cvta_generic_to_shared(p); }
__device__ __forceinline__ void ldsm4(u32 r[4], u32 addr) {
    asm volatile("ldmatrix.sync.aligned.m8n8.x4.shared.b16 {%0,%1,%2,%3}, [%4];"
                 : "=r"(r[0]), "=r"(r[1]), "=r"(r[2]), "=r"(r[3]) : "r"(addr));
}
__device__ __forceinline__ void ldsm2(u32 r[2], u32 addr) {
    asm volatile("ldmatrix.sync.aligned.m8n8.x2.shared.b16 {%0,%1}, [%2];"
                 : "=r"(r[0]), "=r"(r[1]) : "r"(addr));
}
__device__ __forceinline__ void ldsm2t(u32 r[2], u32 addr) {
    asm volatile("ldmatrix.sync.aligned.m8n8.x2.trans.shared.b16 {%0,%1}, [%2];"
                 : "=r"(r[0]), "=r"(r[1]) : "r"(addr));
}
__device__ __forceinline__ void mma16816(float d[4], const u32 a[4], const u32 b[2]) {
    asm volatile("mma.sync.aligned.m16n8k16.row.col.f32.bf16.bf16.f32 "
                 "{%0,%1,%2,%3}, {%4,%5,%6,%7}, {%8,%9}, {%0,%1,%2,%3};"
                 : "+f"(d[0]), "+f"(d[1]), "+f"(d[2]), "+f"(d[3])
                 : "r"(a[0]), "r"(a[1]), "r"(a[2]), "r"(a[3]), "r"(b[0]), "r"(b[1]));
}
__device__ __forceinline__ unsigned short bfbits(__nv_bfloat16 h) {
    return *reinterpret_cast<unsigned short*>(&h);
}

__device__ float g_pb[NH * NTOK * NTOK];
__device__ float g_pbm[NWIN * NH * NTOK * NTOK];
__device__ float g_lam;
// weights in mma B-fragment order:
// [chunk 0..11][img hi/lo][kt 0..7][nt 0..7][lane 0..31] -> u64 {b0,b1}
__device__ u64 g_wf[12 * 2 * 8 * 8 * 32];

// ---------------------------------------------------------------------------
__global__ void prep1_kernel(const float* __restrict__ Wp1, const float* __restrict__ bp1,
                             const float* __restrict__ Wp2, const float* __restrict__ bp2,
                             const float* __restrict__ lq1, const float* __restrict__ lk1,
                             const float* __restrict__ lq2, const float* __restrict__ lk2)
{
    int idx = blockIdx.x * blockDim.x + threadIdx.x;
    if (idx < NTOK * NTOK) {
        int i = idx >> 6, j = idx & 63;
        float dx = (float)(i & 7) - (float)(j & 7);
        float dy = -((float)(i >> 3) - (float)(j >> 3));
        float r  = sqrtf(dx * dx + dy * dy + 1e-9f);
        float th = atan2f(dx, dy);
        float p0 = r * 0.10101525445522107f;
        float p1 = (th + 3.14159265358979323846f) * 0.15915494309189535f;
        float o0 = __ldg(bp2 + 0), o1 = __ldg(bp2 + 1), o2 = __ldg(bp2 + 2), o3 = __ldg(bp2 + 3);
        for (int jj = 0; jj < 64; jj++) {
            float hv = fmaf(p0, __ldg(Wp1 + jj * 2), fmaf(p1, __ldg(Wp1 + jj * 2 + 1), __ldg(bp1 + jj)));
            float g  = 0.5f * hv * (1.0f + erff(hv * 0.7071067811865476f));
            o0 = fmaf(g, __ldg(Wp2 +       jj), o0);
            o1 = fmaf(g, __ldg(Wp2 +  64 + jj), o1);
            o2 = fmaf(g, __ldg(Wp2 + 128 + jj), o2);
            o3 = fmaf(g, __ldg(Wp2 + 192 + jj), o3);
        }
        g_pb[          idx] = o0;
        g_pb[ 4096 +   idx] = o1;
        g_pb[ 8192 +   idx] = o2;
        g_pb[12288 +   idx] = o3;
    }
    if (idx == 0) {
        float s1 = 0.f, s2 = 0.f;
        for (int k = 0; k < 16; k++) {
            s1 = fmaf(__ldg(lq1 + k), __ldg(lk1 + k), s1);
            s2 = fmaf(__ldg(lq2 + k), __ldg(lk2 + k), s2);
        }
        g_lam = expf(s1) - expf(s2) + 0.2f;
    }
}

__global__ void prep2_kernel(const float* __restrict__ mask)
{
    int idx = blockIdx.x * 256 + threadIdx.x;
    int rest = idx & 16383;
    int w    = idx >> 14;
    int nm   = idx & 4095;
    g_pbm[idx] = g_pb[rest] + __ldg(mask + w * 4096 + nm);
}

// Prep 3: weights -> hi/lo bf16, directly in mma B-fragment order.
// Folds QSCALE into q/q2 and subln*(1-lambda_init) into proj.
__global__ void prepw_kernel(const float* __restrict__ Wqkv,
                             const float* __restrict__ Wqkv2,
                             const float* __restrict__ Wproj,
                             const float* __restrict__ subln)
{
    int idx = blockIdx.x * 256 + threadIdx.x;   // 0..49151 (one u64 each)
    int lane  = idx & 31;
    int nt    = (idx >> 5) & 7;
    int kt    = (idx >> 8) & 7;
    int img   = (idx >> 11) & 1;
    int chunk = idx >> 12;
    int cg = chunk * 64 + nt * 8 + (lane >> 2);      // global output column
    int k0 = kt * 16 + (lane & 3) * 2;

    float v[4];
    int kk[4] = {k0, k0 + 1, k0 + 8, k0 + 9};
    #pragma unroll
    for (int j = 0; j < 4; j++) {
        int k = kk[j];
        float s, w;
        if (cg < 384)      { w = __ldg(Wqkv  + cg * 128 + k);         s = (cg < 128) ? QSCALE : 1.0f; }
        else if (cg < 640) { w = __ldg(Wqkv2 + (cg - 384) * 128 + k); s = (cg < 512) ? QSCALE : 1.0f; }
        else               { w = __ldg(Wproj + (cg - 640) * 128 + k); s = __ldg(subln + (k & 31)) * OUTS; }
        v[j] = w * s;
    }
    unsigned short b[4];
    #pragma unroll
    for (int j = 0; j < 4; j++) {
        __nv_bfloat16 h = __float2bfloat16(v[j]);
        if (img == 0) b[j] = bfbits(h);
        else          b[j] = bfbits(__float2bfloat16(v[j] - __bfloat162float(h)));
    }
    g_wf[idx] = (u64)b[0] | ((u64)b[1] << 16) | ((u64)b[2] << 32) | ((u64)b[3] << 48);
}

// ---------------------------------------------------------------------------
// Main fused kernel, 512 threads. smem bytes (total 229376):
//   A [0,32768):       x bf16 hi/lo images  -> os fp32 SWZ tile after QKV
//   B [32768,65536):   att fp32 (stride 68) / P hi@32768 lo@40960 / os hi/lo images
//   C [65536,229376):  images: q 65536/81920, k 98304/114688, q2 131072/147456,
//                      k2 163840/180224, v 196608/212992
// ---------------------------------------------------------------------------
__global__ __launch_bounds__(NTHR) void wattn_kernel(
    const float* __restrict__ x,
    const float* __restrict__ bqkv, const float* __restrict__ bqkv2,
    const float* __restrict__ bproj,
    float* __restrict__ out)
{
    extern __shared__ float sm[];
    char* smc = (char*)sm;
    float* os  = sm;                       // region A (after QKV)
    float* att = sm + 8192;                // region B

    const int b = blockIdx.x;
    const int t = threadIdx.x;
    const int w = t >> 5, lid = t & 31;
    const int mg = w & 3, wg = w >> 2;
    const u32 smb = sptr(sm);

    // ---- load x, split to bf16 hi/lo swizzled images (region A) ----
    const float4* xg = (const float4*)(x + (size_t)b * (NTOK * DIM));
    #pragma unroll
    for (int i = 0; i < 4; i++) {
        int idx = t + i * NTHR;
        int token = idx >> 5, kb = idx & 31;
        float4 v = __ldg(xg + idx);
        __nv_bfloat16 h0 = __float2bfloat16(v.x), h1 = __float2bfloat16(v.y);
        __nv_bfloat16 h2 = __float2bfloat16(v.z), h3 = __float2bfloat16(v.w);
        __nv_bfloat16 l0 = __float2bfloat16(v.x - __bfloat162float(h0));
        __nv_bfloat16 l1 = __float2bfloat16(v.y - __bfloat162float(h1));
        __nv_bfloat16 l2 = __float2bfloat16(v.z - __bfloat162float(h2));
        __nv_bfloat16 l3 = __float2bfloat16(v.w - __bfloat162float(h3));
        u64 hp = (u64)bfbits(h0) | ((u64)bfbits(h1) << 16) | ((u64)bfbits(h2) << 32) | ((u64)bfbits(h3) << 48);
        u64 lp = (u64)bfbits(l0) | ((u64)bfbits(l1) << 16) | ((u64)bfbits(l2) << 32) | ((u64)bfbits(l3) << 48);
        int sw = BSW(token, kb * 8);
        *(u64*)(smc + sw)         = hp;
        *(u64*)(smc + 16384 + sw) = lp;
    }
    __syncthreads();

    // ---- QKV: A-fragments preloaded once; B-fragments direct from gmem ----
    {
        u32 xah[8][4], xal[8][4];
        {
            const int ar = mg * 16 + (lid & 15);
            const int ak = (lid & 16);
            #pragma unroll
            for (int kt = 0; kt < 8; kt++) {
                int off = BSW(ar, kt * 32 + ak);
                ldsm4(xah[kt], smb + off);
                ldsm4(xal[kt], smb + 16384 + off);
            }
        }

        #pragma unroll 1
        for (int ch = 0; ch < 10; ch++) {
            const u64* wf = g_wf + ch * 4096 + wg * 64 + lid;   // nt base = wg*2
            float d[2][4];
            #pragma unroll
            for (int nt = 0; nt < 2; nt++)
                #pragma unroll
                for (int i = 0; i < 4; i++) d[nt][i] = 0.f;

            #pragma unroll
            for (int kt = 0; kt < 8; kt++) {
                #pragma unroll
                for (int ntj = 0; ntj < 2; ntj++) {
                    u64 bhv = __ldg(wf + kt * 256 + ntj * 32);
                    u64 blv = __ldg(wf + 2048 + kt * 256 + ntj * 32);
                    u32 bh[2] = {(u32)bhv, (u32)(bhv >> 32)};
                    u32 bl[2] = {(u32)blv, (u32)(blv >> 32)};
                    mma16816(d[ntj], xah[kt], bh);
                    mma16816(d[ntj], xah[kt], bl);
                    mma16816(d[ntj], xal[kt], bh);
                }
            }

            const int ten = ch >> 1;                  // 0:q 1:k 2:v 3:q2 4:k2
            const float bmult = (ten == 0 || ten == 3) ? QSCALE : 1.0f;
            const float* bsrc = (ten < 3) ? (bqkv + ten * 128) : (bqkv2 + (ten - 3) * 128);
            const int r0 = mg * 16 + (lid >> 2);
            const int ibase = (ten == 0) ? 65536 : (ten == 1) ? 98304
                            : (ten == 2) ? 196608 : (ten == 3) ? 131072 : 163840;
            char* img = smc + ibase;
            #pragma unroll
            for (int nt = 0; nt < 2; nt++) {
                int tc = (ch & 1) * 64 + wg * 16 + nt * 8 + 2 * (lid & 3);
                float b0 = __ldg(bsrc + tc) * bmult, b1 = __ldg(bsrc + tc + 1) * bmult;
                float v0 = d[nt][0] + b0, v1 = d[nt][1] + b1;
                float v2 = d[nt][2] + b0, v3 = d[nt][3] + b1;
                int c2 = tc * 2;
                __nv_bfloat16 h0 = __float2bfloat16(v0), h1 = __float2bfloat16(v1);
                __nv_bfloat16 h2 = __float2bfloat16(v2), h3 = __float2bfloat16(v3);
                u32 hp01 = (u32)bfbits(h0) | ((u32)bfbits(h1) << 16);
                u32 hp23 = (u32)bfbits(h2) | ((u32)bfbits(h3) << 16);
                __nv_bfloat16 l0 = __float2bfloat16(v0 - __bfloat162float(h0));
                __nv_bfloat16 l1 = __float2bfloat16(v1 - __bfloat162float(h1));
                __nv_bfloat16 l2 = __float2bfloat16(v2 - __bfloat162float(h2));
                __nv_bfloat16 l3 = __float2bfloat16(v3 - __bfloat162float(h3));
                u32 lp01 = (u32)bfbits(l0) | ((u32)bfbits(l1) << 16);
                u32 lp23 = (u32)bfbits(l2) | ((u32)bfbits(l3) << 16);
                int s0 = BSW(r0, c2), s1 = BSW(r0 + 8, c2);
                *(u32*)(img + s0)         = hp01;
                *(u32*)(img + 16384 + s0) = lp01;
                *(u32*)(img + s1)         = hp23;
                *(u32*)(img + 16384 + s1) = lp23;
            }
        }
    }
    __syncthreads();

    // ---- differential attention: fully tensor-core (unchanged) ----
    const float lam = g_lam;
    const float* pbm = g_pbm + (size_t)(b % NWIN) * (NH * NTOK * NTOK);
    const int n = t >> 3, qd = t & 7;

    #pragma unroll 1
    for (int h = 0; h < NH; h++) {
        // -- logits via mma.sync: d1 = q.k^T, d2 = q2.k2^T --
        {
            float d1[2][4], d2[2][4];
            #pragma unroll
            for (int nt = 0; nt < 2; nt++)
                #pragma unroll
                for (int i = 0; i < 4; i++) { d1[nt][i] = 0.f; d2[nt][i] = 0.f; }
            const int ar = mg * 16 + (lid & 15);
            const int abyte = h * 64 + (lid & 16);
            const int bc = wg * 16 + (lid & 7);
            const int bbyte = h * 64 + ((lid & 8) << 1);
            #pragma unroll
            for (int ks = 0; ks < 2; ks++) {
                u32 aoff = BSW(ar, abyte + ks * 32);
                u32 qh[4], ql[4], q2h[4], q2l[4];
                ldsm4(qh,  smb +  65536 + aoff);
                ldsm4(ql,  smb +  81920 + aoff);
                ldsm4(q2h, smb + 131072 + aoff);
                ldsm4(q2l, smb + 147456 + aoff);
                #pragma unroll
                for (int nt = 0; nt < 2; nt++) {
                    u32 boff = BSW(bc + nt * 8, bbyte + ks * 32);
                    u32 kh[2], kl[2], k2h[2], k2l[2];
                    ldsm2(kh,  smb +  98304 + boff);
                    ldsm2(kl,  smb + 114688 + boff);
                    ldsm2(k2h, smb + 163840 + boff);
                    ldsm2(k2l, smb + 180224 + boff);
                    mma16816(d1[nt], qh, kh);
                    mma16816(d1[nt], qh, kl);
                    mma16816(d1[nt], ql, kh);
                    mma16816(d2[nt], q2h, k2h);
                    mma16816(d2[nt], q2h, k2l);
                    mma16816(d2[nt], q2l, k2h);
                }
            }
            const int r0 = mg * 16 + (lid >> 2);
            #pragma unroll
            for (int nt = 0; nt < 2; nt++) {
                int col = wg * 16 + nt * 8 + 2 * (lid & 3);
                float2 p0 = __ldg((const float2*)(pbm + h * 4096 + r0 * 64 + col));
                float2 p1 = __ldg((const float2*)(pbm + h * 4096 + (r0 + 8) * 64 + col));
                *(float2*)(att + r0 * 68 + col) =
                    make_float2(fmaf(-lam, d2[nt][0], d1[nt][0]) + p0.x,
                                fmaf(-lam, d2[nt][1], d1[nt][1]) + p0.y);
                *(float2*)(att + (r0 + 8) * 68 + col) =
                    make_float2(fmaf(-lam, d2[nt][2], d1[nt][2]) + p1.x,
                                fmaf(-lam, d2[nt][3], d1[nt][3]) + p1.y);
            }
        }
        __syncthreads();

        // -- softmax: lane owns 8 contiguous cols [qd*8, qd*8+8) of row n --
        float p[8];
        {
            float4 L0 = *(const float4*)(att + n * 68 + qd * 8);
            float4 L1 = *(const float4*)(att + n * 68 + qd * 8 + 4);
            p[0] = L0.x; p[1] = L0.y; p[2] = L0.z; p[3] = L0.w;
            p[4] = L1.x; p[5] = L1.y; p[6] = L1.z; p[7] = L1.w;
        }
        __syncthreads();   // all att reads done before P overwrites region B
        {
            float M = p[0];
            #pragma unroll
            for (int j = 1; j < 8; j++) M = fmaxf(M, p[j]);
            M = fmaxf(M, __shfl_xor_sync(0xffffffffu, M, 1));
            M = fmaxf(M, __shfl_xor_sync(0xffffffffu, M, 2));
            M = fmaxf(M, __shfl_xor_sync(0xffffffffu, M, 4));
            float S = 0.f;
            #pragma unroll
            for (int j = 0; j < 8; j++) { p[j] = __expf(p[j] - M); S += p[j]; }
            S += __shfl_xor_sync(0xffffffffu, S, 1);
            S += __shfl_xor_sync(0xffffffffu, S, 2);
            S += __shfl_xor_sync(0xffffffffu, S, 4);
            float inv = 1.0f / S;
            u32 hp[4], lp[4];
            #pragma unroll
            for (int j = 0; j < 4; j++) {
                float v0 = p[2 * j] * inv, v1 = p[2 * j + 1] * inv;
                __nv_bfloat16 h0 = __float2bfloat16(v0), h1 = __float2bfloat16(v1);
                hp[j] = (u32)bfbits(h0) | ((u32)bfbits(h1) << 16);
                __nv_bfloat16 l0 = __float2bfloat16(v0 - __bfloat162float(h0));
                __nv_bfloat16 l1 = __float2bfloat16(v1 - __bfloat162float(h1));
                lp[j] = (u32)bfbits(l0) | ((u32)bfbits(l1) << 16);
            }
            int sw = BSW128(n, qd * 16);
            *(uint4*)(smc + 32768 + sw) = make_uint4(hp[0], hp[1], hp[2], hp[3]);
            *(uint4*)(smc + 40960 + sw) = make_uint4(lp[0], lp[1], lp[2], lp[3]);
        }
        __syncthreads();

        // -- o = P @ V via mma.sync (V fragment via ldmatrix.trans) --
        {
            float d[4] = {0.f, 0.f, 0.f, 0.f};
            const int ar = mg * 16 + (lid & 15);
            const int ak = (lid & 16);
            #pragma unroll
            for (int ks = 0; ks < 4; ks++) {
                u32 ph[4], pl[4];
                u32 paddr = smb + 32768 + BSW128(ar, ks * 32 + ak);
                ldsm4(ph, paddr);
                ldsm4(pl, paddr + 8192);
                u32 vh[2], vl[2];
                u32 vaddr = smb + 196608 + BSW(ks * 16 + (lid & 15), h * 64 + wg * 16);
                ldsm2t(vh, vaddr);
                ldsm2t(vl, vaddr + 16384);
                mma16816(d, ph, vh);
                mma16816(d, ph, vl);
                mma16816(d, pl, vh);
            }
            const int r0 = mg * 16 + (lid >> 2);
            int c = h * 32 + wg * 8 + 2 * (lid & 3);
            int g = c >> 2, sub = c & 3;
            *(float2*)(os + SWZ(r0, g) * 4 + sub)     = make_float2(d[0], d[1]);
            *(float2*)(os + SWZ(r0 + 8, g) * 4 + sub) = make_float2(d[2], d[3]);
        }
        __syncthreads();   // P/att dead before next head's logit stores
    }

    // ---- RMSNorm over head_dim, in place ----
    {
        #pragma unroll
        for (int h = 0; h < NH; h++) {
            int g = h * 8 + qd;
            float4 v4 = ((const float4*)os)[SWZ(n, g)];
            float s = v4.x * v4.x + v4.y * v4.y + v4.z * v4.z + v4.w * v4.w;
            s += __shfl_xor_sync(0xffffffffu, s, 1);
            s += __shfl_xor_sync(0xffffffffu, s, 2);
            s += __shfl_xor_sync(0xffffffffu, s, 4);
            float rs = rsqrtf(s * (1.0f / 32.0f) + 1e-9f);
            v4.x *= rs; v4.y *= rs; v4.z *= rs; v4.w *= rs;
            ((float4*)os)[SWZ(n, g)] = v4;
        }
    }
    __syncthreads();

    // ---- convert os -> bf16 hi/lo images in region B ----
    #pragma unroll
    for (int i = 0; i < 4; i++) {
        int idx = t + i * NTHR;
        int token = idx >> 5, g4 = idx & 31;
        float4 v = ((const float4*)os)[SWZ(token, g4)];
        __nv_bfloat16 h0 = __float2bfloat16(v.x), h1 = __float2bfloat16(v.y);
        __nv_bfloat16 h2 = __float2bfloat16(v.z), h3 = __float2bfloat16(v.w);
        __nv_bfloat16 l0 = __float2bfloat16(v.x - __bfloat162float(h0));
        __nv_bfloat16 l1 = __float2bfloat16(v.y - __bfloat162float(h1));
        __nv_bfloat16 l2 = __float2bfloat16(v.z - __bfloat162float(h2));
        __nv_bfloat16 l3 = __float2bfloat16(v.w - __bfloat162float(h3));
        u64 hp = (u64)bfbits(h0) | ((u64)bfbits(h1) << 16) | ((u64)bfbits(h2) << 32) | ((u64)bfbits(h3) << 48);
        u64 lp = (u64)bfbits(l0) | ((u64)bfbits(l1) << 16) | ((u64)bfbits(l2) << 32) | ((u64)bfbits(l3) << 48);
        int sw = BSW(token, g4 * 8);
        *(u64*)(smc + 32768 + sw) = hp;
        *(u64*)(smc + 49152 + sw) = lp;
    }
    __syncthreads();

    // ---- proj: A-fragments from os images, B-fragments from gmem ----
    {
        u32 oah[8][4], oal[8][4];
        {
            const int ar = mg * 16 + (lid & 15);
            const int ak = (lid & 16);
            #pragma unroll
            for (int kt = 0; kt < 8; kt++) {
                int off = BSW(ar, kt * 32 + ak);
                ldsm4(oah[kt], smb + 32768 + off);
                ldsm4(oal[kt], smb + 49152 + off);
            }
        }
        float* og = out + (size_t)b * (NTOK * DIM);
        #pragma unroll 1
        for (int pc = 0; pc < 2; pc++) {
            const u64* wf = g_wf + (10 + pc) * 4096 + wg * 64 + lid;
            float d[2][4];
            #pragma unroll
            for (int nt = 0; nt < 2; nt++)
                #pragma unroll
                for (int i = 0; i < 4; i++) d[nt][i] = 0.f;
            #pragma unroll
            for (int kt = 0; kt < 8; kt++) {
                #pragma unroll
                for (int ntj = 0; ntj < 2; ntj++) {
                    u64 bhv = __ldg(wf + kt * 256 + ntj * 32);
                    u64 blv = __ldg(wf + 2048 + kt * 256 + ntj * 32);
                    u32 bh[2] = {(u32)bhv, (u32)(bhv >> 32)};
                    u32 bl[2] = {(u32)blv, (u32)(blv >> 32)};
                    mma16816(d[ntj], oah[kt], bh);
                    mma16816(d[ntj], oah[kt], bl);
                    mma16816(d[ntj], oal[kt], bh);
                }
            }
            const int r0 = mg * 16 + (lid >> 2);
            #pragma unroll
            for (int nt = 0; nt < 2; nt++) {
                int cg = pc * 64 + wg * 16 + nt * 8 + 2 * (lid & 3);
                float b0 = __ldg(bproj + cg), b1 = __ldg(bproj + cg + 1);
                *(float2*)(og + r0 * 128 + cg)       = make_float2(d[nt][0] + b0, d[nt][1] + b1);
                *(float2*)(og + (r0 + 8) * 128 + cg) = make_float2(d[nt][2] + b0, d[nt][3] + b1);
            }
        }
    }
}

// ---------------------------------------------------------------------------
extern "C" void kernel_launch(void* const* d_in, const int* in_sizes, int n_in,
                              void* d_out, int out_size)
{
    const float* x      = (const float*)d_in[0];
    const float* mask   = (const float*)d_in[1];
    const float* Wqkv   = (const float*)d_in[2];
    const float* bqkv   = (const float*)d_in[3];
    const float* Wqkv2  = (const float*)d_in[4];
    const float* bqkv2  = (const float*)d_in[5];
    const float* Wp1    = (const float*)d_in[6];
    const float* bp1    = (const float*)d_in[7];
    const float* Wp2    = (const float*)d_in[8];
    const float* bp2    = (const float*)d_in[9];
    const float* lq1    = (const float*)d_in[10];
    const float* lk1    = (const float*)d_in[11];
    const float* lq2    = (const float*)d_in[12];
    const float* lk2    = (const float*)d_in[13];
    const float* subln  = (const float*)d_in[14];
    const float* Wproj  = (const float*)d_in[15];
    const float* bproj  = (const float*)d_in[16];
    float* out = (float*)d_out;

    const int SMEM = 229376;
    cudaFuncSetAttribute(wattn_kernel, cudaFuncAttributeMaxDynamicSharedMemorySize, SMEM);

    prep1_kernel<<<16, 256>>>(Wp1, bp1, Wp2, bp2, lq1, lk1, lq2, lk2);
    prep2_kernel<<<(NWIN * NH * NTOK * NTOK) / 256, 256>>>(mask);
    prepw_kernel<<<192, 256>>>(Wqkv, Wqkv2, Wproj, subln);
    wattn_kernel<<<B_TOT, NTHR, SMEM>>>(x, bqkv, bqkv2, bproj, out);
}